// round 1
// baseline (speedup 1.0000x reference)
#include <cuda_runtime.h>
#include <math.h>

// Problem constants (fixed shapes)
#define NN 100000
#define EE 1600000
#define HH 128
#define BB 16
#define MM 2048
#define LL 3

// -------- static device scratch (no allocations allowed) --------
__device__ float g_h[(size_t)NN * HH];   // node hidden state
__device__ float g_A[(size_t)NN * HH];   // h @ Wm_top
__device__ float g_B[(size_t)NN * HH];   // h @ Wm_bot
__device__ int   g_src[EE];
__device__ int   g_tgt[EE];
__device__ int   g_col[EE];              // CSR column (src) list grouped by tgt
__device__ int   g_deg[NN];
__device__ int   g_off[NN];
__device__ int   g_cursor[NN];
__device__ int   g_batchi[NN];
__device__ int   g_bsums[128];
__device__ float g_gsum[BB * HH];
__device__ int   g_cnt[BB];
__device__ float g_t1[BB * 2 * HH];
__device__ int   g_flags;                // bit0: edges stored int32, bit1: batch stored int32

// ----------------------------------------------------------------
__global__ void zero_kernel() {
    int i = blockIdx.x * blockDim.x + threadIdx.x;
    if (i < NN) g_deg[i] = 0;
    if (i < BB * HH) g_gsum[i] = 0.0f;
    if (i < BB) g_cnt[i] = 0;
    if (i == 0) g_flags = 0;
}

// Detect whether edge_index / batch were materialized as int32 or int64.
// Sampled int64 reads stay in-bounds under either interpretation.
__global__ void detect_kernel(const void* __restrict__ ep, const void* __restrict__ bp) {
    int j = threadIdx.x;  // 256 threads
    // edges: sample positions in [0, E) as int64 elements
    long long pos = (long long)j * (EE / 256);
    long long v = ((const long long*)ep)[pos];
    if (v < 0 || v >= NN) atomicOr(&g_flags, 1);
    // batch: sample positions in [N/4, N/4+256) (word index < N/2 -> safe)
    long long bpos = (long long)(NN / 4) + j;
    long long bv = ((const long long*)bp)[bpos];
    if (bv < 0 || bv >= BB) atomicOr(&g_flags, 2);
}

__global__ void convert_kernel(const void* __restrict__ ep, const void* __restrict__ bp) {
    int f = g_flags;
    long long i = (long long)blockIdx.x * blockDim.x + threadIdx.x;
    if (i < EE) {
        long long s, t;
        if (f & 1) {
            s = ((const int*)ep)[i];
            t = ((const int*)ep)[EE + i];
        } else {
            s = ((const long long*)ep)[i];
            t = ((const long long*)ep)[EE + i];
        }
        g_src[i] = (int)s;
        g_tgt[i] = (int)t;
    }
    if (i < NN) {
        int b = (f & 2) ? ((const int*)bp)[i] : (int)((const long long*)bp)[i];
        g_batchi[i] = b;
        atomicAdd(&g_cnt[b], 1);
    }
}

__global__ void hist_kernel() {
    long long i = (long long)blockIdx.x * blockDim.x + threadIdx.x;
    if (i < EE) atomicAdd(&g_deg[g_tgt[i]], 1);
}

// -------- 3-phase exclusive scan over g_deg -> g_off --------
__global__ void scan1_kernel() {
    __shared__ int sh[1024];
    int t = threadIdx.x;
    int i = blockIdx.x * 1024 + t;
    int v = (i < NN) ? g_deg[i] : 0;
    sh[t] = v;
    __syncthreads();
#pragma unroll
    for (int s = 1; s < 1024; s <<= 1) {
        int x = (t >= s) ? sh[t - s] : 0;
        __syncthreads();
        sh[t] += x;
        __syncthreads();
    }
    if (i < NN) g_off[i] = sh[t] - v;  // exclusive within block
    if (t == 1023) g_bsums[blockIdx.x] = sh[1023];
}

__global__ void scan2_kernel(int nb) {
    __shared__ int sh[128];
    int t = threadIdx.x;  // 128 threads, nb <= 128
    int v = (t < nb) ? g_bsums[t] : 0;
    sh[t] = v;
    __syncthreads();
#pragma unroll
    for (int s = 1; s < 128; s <<= 1) {
        int x = (t >= s) ? sh[t - s] : 0;
        __syncthreads();
        sh[t] += x;
        __syncthreads();
    }
    if (t < nb) g_bsums[t] = sh[t] - v;  // exclusive block prefix
}

__global__ void scan3_kernel() {
    int i = blockIdx.x * 1024 + threadIdx.x;
    if (i < NN) {
        int o = g_off[i] + g_bsums[blockIdx.x];
        g_off[i] = o;
        g_cursor[i] = o;
    }
}

__global__ void fill_kernel() {
    long long i = (long long)blockIdx.x * blockDim.x + threadIdx.x;
    if (i < EE) {
        int t = g_tgt[i];
        int p = atomicAdd(&g_cursor[t], 1);
        g_col[p] = g_src[i];
    }
}

// -------- fp32 SIMT GEMM: out[n,128] = A[n,128] @ W[128,128] (+bias) --------
__global__ void __launch_bounds__(256) gemm128(const float* __restrict__ A,
                                               const float* __restrict__ W,
                                               const float* __restrict__ bias,
                                               float* __restrict__ out, int nrows) {
    __shared__ __align__(16) float As[64][16];
    __shared__ __align__(16) float Ws[16][128];
    const int tid = threadIdx.x;
    const int tx = tid & 31;   // col group (x4)
    const int ty = tid >> 5;   // row group (x8)
    const int rowBase = blockIdx.x * 64;
    const int a_row = tid >> 2;
    const int a_c = (tid & 3) * 4;
    const int gr = rowBase + a_row;
    const float* Arow = A + (size_t)gr * HH;

    float acc[8][4];
#pragma unroll
    for (int i = 0; i < 8; i++)
#pragma unroll
        for (int j = 0; j < 4; j++) acc[i][j] = 0.0f;

    for (int k0 = 0; k0 < HH; k0 += 16) {
        float4 av = make_float4(0.f, 0.f, 0.f, 0.f);
        if (gr < nrows) av = *(const float4*)(Arow + k0 + a_c);
        *(float4*)&As[a_row][a_c] = av;
#pragma unroll
        for (int i = 0; i < 2; i++) {
            int idx = tid + i * 256;
            int wr = idx >> 5;
            int wc = (idx & 31) * 4;
            *(float4*)&Ws[wr][wc] = *(const float4*)(W + (size_t)(k0 + wr) * HH + wc);
        }
        __syncthreads();
#pragma unroll
        for (int kk = 0; kk < 16; kk++) {
            float4 wq = *(const float4*)&Ws[kk][tx * 4];
#pragma unroll
            for (int i = 0; i < 8; i++) {
                float a = As[ty * 8 + i][kk];
                acc[i][0] = fmaf(a, wq.x, acc[i][0]);
                acc[i][1] = fmaf(a, wq.y, acc[i][1]);
                acc[i][2] = fmaf(a, wq.z, acc[i][2]);
                acc[i][3] = fmaf(a, wq.w, acc[i][3]);
            }
        }
        __syncthreads();
    }

    float bx = 0.f, by = 0.f, bz = 0.f, bw = 0.f;
    if (bias) {
        bx = bias[tx * 4 + 0];
        by = bias[tx * 4 + 1];
        bz = bias[tx * 4 + 2];
        bw = bias[tx * 4 + 3];
    }
#pragma unroll
    for (int i = 0; i < 8; i++) {
        int r = rowBase + ty * 8 + i;
        if (r < nrows) {
            float4 o;
            o.x = acc[i][0] + bx;
            o.y = acc[i][1] + by;
            o.z = acc[i][2] + bz;
            o.w = acc[i][3] + bw;
            *(float4*)(out + (size_t)r * HH + tx * 4) = o;
        }
    }
}

// -------- fused aggregate + residual + relu (atomic-free via CSR) --------
// h[t] = relu(h[t] + deg[t]*(B[t]+bm) + sum_{incoming e} A[src[e]])
__global__ void __launch_bounds__(128) gather_relu(const float* __restrict__ bm) {
    int t = blockIdx.x;
    int c = threadIdx.x;
    int d = g_deg[t];
    int o = g_off[t];
    float acc0 = (float)d * (g_B[(size_t)t * HH + c] + bm[c]);
    float acc1 = 0.0f;
    int i = 0;
    for (; i + 2 <= d; i += 2) {
        int s0 = g_col[o + i];
        int s1 = g_col[o + i + 1];
        acc0 += g_A[(size_t)s0 * HH + c];
        acc1 += g_A[(size_t)s1 * HH + c];
    }
    if (i < d) acc0 += g_A[(size_t)g_col[o + i] * HH + c];
    size_t idx = (size_t)t * HH + c;
    float v = g_h[idx] + acc0 + acc1;
    g_h[idx] = v > 0.0f ? v : 0.0f;
}

// -------- per-graph mean pool (batch is sorted; block partial sums) --------
__global__ void __launch_bounds__(128) pool_kernel() {
    int c = threadIdx.x;
    int n0 = blockIdx.x * 512;
    if (n0 >= NN) return;
    int n1 = n0 + 512;
    if (n1 > NN) n1 = NN;
    int curb = g_batchi[n0];
    float acc = 0.0f;
    for (int n = n0; n < n1; n++) {
        int b = g_batchi[n];
        if (b != curb) {
            atomicAdd(&g_gsum[curb * HH + c], acc);
            acc = 0.0f;
            curb = b;
        }
        acc += g_h[(size_t)n * HH + c];
    }
    atomicAdd(&g_gsum[curb * HH + c], acc);
}

// -------- readout --------
__global__ void r1_kernel(const float* __restrict__ W1, const float* __restrict__ b1) {
    int idx = blockIdx.x * blockDim.x + threadIdx.x;
    if (idx >= BB * 2 * HH) return;
    int b = idx >> 8;        // / 256
    int j = idx & 255;
    int cnt = g_cnt[b];
    float inv = 1.0f / (float)(cnt > 0 ? cnt : 1);
    float s = 0.0f;
#pragma unroll 8
    for (int k = 0; k < HH; k++) s = fmaf(g_gsum[b * HH + k], W1[(size_t)k * 256 + j], s);
    s = s * inv + b1[j];
    g_t1[idx] = s > 0.0f ? s : 0.0f;
}

__global__ void r2_kernel(const float* __restrict__ W2, const float* __restrict__ b2,
                          float* __restrict__ out) {
    int idx = blockIdx.x * blockDim.x + threadIdx.x;
    if (idx >= BB * MM) return;
    int b = idx >> 11;       // / 2048
    int m = idx & 2047;
    float s = b2[m];
#pragma unroll 8
    for (int k = 0; k < 2 * HH; k++)
        s = fmaf(g_t1[b * 2 * HH + k], W2[(size_t)k * MM + m], s);
    float sig = 1.0f / (1.0f + expf(-s));
    out[idx] = sig * 6.283185307179586f;
}

// ----------------------------------------------------------------
extern "C" void kernel_launch(void* const* d_in, const int* in_sizes, int n_in,
                              void* d_out, int out_size) {
    const float* x       = (const float*)d_in[0];
    const void*  eidx    = d_in[1];
    const void*  batchp  = d_in[2];
    const float* W_embed = (const float*)d_in[3];
    const float* b_embed = (const float*)d_in[4];
    const float* Wm      = (const float*)d_in[5];
    const float* bm      = (const float*)d_in[6];
    const float* W1      = (const float*)d_in[7];
    const float* b1      = (const float*)d_in[8];
    const float* W2      = (const float*)d_in[9];
    const float* b2      = (const float*)d_in[10];
    float* out = (float*)d_out;

    int nrows = in_sizes[0] / HH;  // N
    if (nrows > NN) nrows = NN;

    void *g_h_p, *g_A_p, *g_B_p;
    cudaGetSymbolAddress(&g_h_p, g_h);
    cudaGetSymbolAddress(&g_A_p, g_A);
    cudaGetSymbolAddress(&g_B_p, g_B);

    const int nb_scan = (NN + 1023) / 1024;
    const int eg = (EE + 255) / 256;
    const int gemm_grid = (nrows + 63) / 64;

    zero_kernel<<<(NN + 255) / 256, 256>>>();
    detect_kernel<<<1, 256>>>(eidx, batchp);
    convert_kernel<<<eg, 256>>>(eidx, batchp);
    hist_kernel<<<eg, 256>>>();
    scan1_kernel<<<nb_scan, 1024>>>();
    scan2_kernel<<<1, 128>>>(nb_scan);
    scan3_kernel<<<nb_scan, 1024>>>();
    fill_kernel<<<eg, 256>>>();

    // embed: h = x @ W_embed + b_embed
    gemm128<<<gemm_grid, 256>>>(x, W_embed, b_embed, (float*)g_h_p, nrows);

    for (int l = 0; l < LL; l++) {
        const float* WA = Wm + (size_t)l * 2 * HH * HH;       // rows 0..127
        const float* WB = WA + (size_t)HH * HH;               // rows 128..255
        gemm128<<<gemm_grid, 256>>>((const float*)g_h_p, WA, nullptr, (float*)g_A_p, nrows);
        gemm128<<<gemm_grid, 256>>>((const float*)g_h_p, WB, nullptr, (float*)g_B_p, nrows);
        gather_relu<<<nrows, 128>>>(bm + (size_t)l * HH);
    }

    pool_kernel<<<(NN + 511) / 512, 128>>>();
    r1_kernel<<<(BB * 2 * HH + 255) / 256, 256>>>(W1, b1);
    r2_kernel<<<(BB * MM + 255) / 256, 256>>>(W2, b2, out);
}

// round 2
// speedup vs baseline: 1.0142x; 1.0142x over previous
#include <cuda_runtime.h>
#include <math.h>

// Problem constants (fixed shapes)
#define NN 100000
#define EE 1600000
#define HH 128
#define BB 16
#define MM 2048
#define LL 3

typedef unsigned long long ull;

// -------- static device scratch (no allocations allowed) --------
__device__ float g_h[(size_t)NN * HH];   // node hidden state
__device__ float g_A[(size_t)NN * HH];   // h @ Wm_top
__device__ float g_B[(size_t)NN * HH];   // h @ Wm_bot
__device__ int   g_src[EE];
__device__ int   g_tgt[EE];
__device__ int   g_col[EE];              // CSR column (src) list grouped by tgt
__device__ int   g_deg[NN];
__device__ int   g_off[NN];
__device__ int   g_cursor[NN];
__device__ int   g_batchi[NN];
__device__ int   g_bsums[128];
__device__ float g_gsum[BB * HH];
__device__ int   g_cnt[BB];
__device__ float g_t1[BB * 2 * HH];
__device__ int   g_flags;                // bit0: edges stored int32, bit1: batch stored int32

// ----------------------------------------------------------------
__global__ void zero_kernel() {
    int i = blockIdx.x * blockDim.x + threadIdx.x;
    if (i < NN) g_deg[i] = 0;
    if (i < BB * HH) g_gsum[i] = 0.0f;
    if (i < BB) g_cnt[i] = 0;
    if (i == 0) g_flags = 0;
}

// Detect whether edge_index / batch were materialized as int32 or int64.
__global__ void detect_kernel(const void* __restrict__ ep, const void* __restrict__ bp) {
    int j = threadIdx.x;  // 256 threads
    long long pos = (long long)j * (EE / 256);
    long long v = ((const long long*)ep)[pos];
    if (v < 0 || v >= NN) atomicOr(&g_flags, 1);
    long long bpos = (long long)(NN / 4) + j;
    long long bv = ((const long long*)bp)[bpos];
    if (bv < 0 || bv >= BB) atomicOr(&g_flags, 2);
}

// convert + degree histogram + batch counts, one pass
__global__ void convert_kernel(const void* __restrict__ ep, const void* __restrict__ bp) {
    int f = g_flags;
    long long i = (long long)blockIdx.x * blockDim.x + threadIdx.x;
    if (i < EE) {
        long long s, t;
        if (f & 1) {
            s = ((const int*)ep)[i];
            t = ((const int*)ep)[EE + i];
        } else {
            s = ((const long long*)ep)[i];
            t = ((const long long*)ep)[EE + i];
        }
        g_src[i] = (int)s;
        g_tgt[i] = (int)t;
        atomicAdd(&g_deg[(int)t], 1);
    }
    if (i < NN) {
        int b = (f & 2) ? ((const int*)bp)[i] : (int)((const long long*)bp)[i];
        g_batchi[i] = b;
        atomicAdd(&g_cnt[b], 1);
    }
}

// -------- 3-phase exclusive scan over g_deg -> g_off --------
__global__ void scan1_kernel() {
    __shared__ int sh[1024];
    int t = threadIdx.x;
    int i = blockIdx.x * 1024 + t;
    int v = (i < NN) ? g_deg[i] : 0;
    sh[t] = v;
    __syncthreads();
#pragma unroll
    for (int s = 1; s < 1024; s <<= 1) {
        int x = (t >= s) ? sh[t - s] : 0;
        __syncthreads();
        sh[t] += x;
        __syncthreads();
    }
    if (i < NN) g_off[i] = sh[t] - v;
    if (t == 1023) g_bsums[blockIdx.x] = sh[1023];
}

__global__ void scan2_kernel(int nb) {
    __shared__ int sh[128];
    int t = threadIdx.x;
    int v = (t < nb) ? g_bsums[t] : 0;
    sh[t] = v;
    __syncthreads();
#pragma unroll
    for (int s = 1; s < 128; s <<= 1) {
        int x = (t >= s) ? sh[t - s] : 0;
        __syncthreads();
        sh[t] += x;
        __syncthreads();
    }
    if (t < nb) g_bsums[t] = sh[t] - v;
}

__global__ void scan3_kernel() {
    int i = blockIdx.x * 1024 + threadIdx.x;
    if (i < NN) {
        int o = g_off[i] + g_bsums[blockIdx.x];
        g_off[i] = o;
        g_cursor[i] = o;
    }
}

__global__ void fill_kernel() {
    long long i = (long long)blockIdx.x * blockDim.x + threadIdx.x;
    if (i < EE) {
        int t = g_tgt[i];
        int p = atomicAdd(&g_cursor[t], 1);
        g_col[p] = g_src[i];
    }
}

// -------- packed-f32x2 GEMM: out[n,128] = A[n,128] @ W[128,128] (+bias) ----
// 128x128 tile per block, 256 threads, 8 rows x 8 cols per thread.
// FFMA2 (fma.rn.f32x2) doubles fp32 FLOP/issue; operands staged pre-packed:
//   AsD stores each A value DUPLICATED -> {a,a} via one LDS.64
//   Ws column pairs read directly as LDS.64 -> {w_c, w_c+1}
__device__ __forceinline__ ull ffma2(ull a, ull b, ull c) {
    asm("fma.rn.f32x2 %0, %1, %2, %0;" : "+l"(c) : "l"(a), "l"(b));
    return c;
}

__global__ void __launch_bounds__(256) gemm_f32x2(const float* __restrict__ A,
                                                  const float* __restrict__ W0,
                                                  const float* __restrict__ W1p,
                                                  const float* __restrict__ bias,
                                                  float* __restrict__ out0,
                                                  float* __restrict__ out1,
                                                  int nrows) {
    const float* W = (blockIdx.y == 0) ? W0 : W1p;
    float* out = (blockIdx.y == 0) ? out0 : out1;

    __shared__ __align__(16) float AsD[16][256];  // duplicated pairs, 16KB
    __shared__ __align__(16) float Ws[16][128];   // 8KB

    const int tid = threadIdx.x;
    const int tx = tid & 15;   // col group
    const int ty = tid >> 4;   // row group (8 rows)
    const int rowBase = blockIdx.x * 128;

    // A staging map: row = tid>>1, k-offset = (tid&1)*8
    const int a_row = tid >> 1;
    const int a_k = (tid & 1) * 8;
    const int gr = rowBase + a_row;
    const bool a_ok = gr < nrows;
    const float* Arow = A + (size_t)gr * HH;

    // W staging map: 16x128 floats; thread loads Ws[w_r][w_c..w_c+7]
    const int w_r = tid >> 4;
    const int w_c = (tid & 15) * 8;

    ull acc[8][4];
#pragma unroll
    for (int r = 0; r < 8; r++)
#pragma unroll
        for (int c = 0; c < 4; c++) acc[r][c] = 0ull;

    const int c0 = tx * 4;        // cols c0..c0+3
    const int c1 = 64 + tx * 4;   // cols c1..c1+3

    for (int k0 = 0; k0 < HH; k0 += 16) {
        float4 v0 = make_float4(0.f, 0.f, 0.f, 0.f);
        float4 v1 = v0;
        if (a_ok) {
            v0 = *(const float4*)(Arow + k0 + a_k);
            v1 = *(const float4*)(Arow + k0 + a_k + 4);
        }
        {
            float av[8] = {v0.x, v0.y, v0.z, v0.w, v1.x, v1.y, v1.z, v1.w};
#pragma unroll
            for (int j = 0; j < 8; j++) {
                unsigned b = __float_as_uint(av[j]);
                ull d = (ull)b | ((ull)b << 32);
                *(ull*)&AsD[a_k + j][2 * a_row] = d;
            }
        }
        *(float4*)&Ws[w_r][w_c]     = *(const float4*)(W + (size_t)(k0 + w_r) * HH + w_c);
        *(float4*)&Ws[w_r][w_c + 4] = *(const float4*)(W + (size_t)(k0 + w_r) * HH + w_c + 4);
        __syncthreads();

#pragma unroll
        for (int kk = 0; kk < 16; kk++) {
            ull wp[4];
            wp[0] = *(const ull*)&Ws[kk][c0];
            wp[1] = *(const ull*)&Ws[kk][c0 + 2];
            wp[2] = *(const ull*)&Ws[kk][c1];
            wp[3] = *(const ull*)&Ws[kk][c1 + 2];
            ull a2[8];
#pragma unroll
            for (int r = 0; r < 8; r++)
                a2[r] = *(const ull*)&AsD[kk][2 * (ty * 8 + r)];
#pragma unroll
            for (int r = 0; r < 8; r++) {
                acc[r][0] = ffma2(a2[r], wp[0], acc[r][0]);
                acc[r][1] = ffma2(a2[r], wp[1], acc[r][1]);
                acc[r][2] = ffma2(a2[r], wp[2], acc[r][2]);
                acc[r][3] = ffma2(a2[r], wp[3], acc[r][3]);
            }
        }
        __syncthreads();
    }

    float b00 = 0.f, b01 = 0.f, b02 = 0.f, b03 = 0.f;
    float b10 = 0.f, b11 = 0.f, b12 = 0.f, b13 = 0.f;
    if (bias) {
        b00 = bias[c0]; b01 = bias[c0 + 1]; b02 = bias[c0 + 2]; b03 = bias[c0 + 3];
        b10 = bias[c1]; b11 = bias[c1 + 1]; b12 = bias[c1 + 2]; b13 = bias[c1 + 3];
    }
#pragma unroll
    for (int r = 0; r < 8; r++) {
        int row = rowBase + ty * 8 + r;
        if (row < nrows) {
            float4 o0, o1;
            o0.x = __uint_as_float((unsigned)acc[r][0])         + b00;
            o0.y = __uint_as_float((unsigned)(acc[r][0] >> 32)) + b01;
            o0.z = __uint_as_float((unsigned)acc[r][1])         + b02;
            o0.w = __uint_as_float((unsigned)(acc[r][1] >> 32)) + b03;
            o1.x = __uint_as_float((unsigned)acc[r][2])         + b10;
            o1.y = __uint_as_float((unsigned)(acc[r][2] >> 32)) + b11;
            o1.z = __uint_as_float((unsigned)acc[r][3])         + b12;
            o1.w = __uint_as_float((unsigned)(acc[r][3] >> 32)) + b13;
            *(float4*)(out + (size_t)row * HH + c0) = o0;
            *(float4*)(out + (size_t)row * HH + c1) = o1;
        }
    }
}

// -------- fused aggregate + residual + relu (atomic-free via CSR) --------
__global__ void __launch_bounds__(128) gather_relu(const float* __restrict__ bm) {
    int t = blockIdx.x;
    int c = threadIdx.x;
    int d = g_deg[t];
    int o = g_off[t];
    float acc0 = (float)d * (g_B[(size_t)t * HH + c] + bm[c]);
    float acc1 = 0.0f;
    int i = 0;
    for (; i + 2 <= d; i += 2) {
        int s0 = g_col[o + i];
        int s1 = g_col[o + i + 1];
        acc0 += g_A[(size_t)s0 * HH + c];
        acc1 += g_A[(size_t)s1 * HH + c];
    }
    if (i < d) acc0 += g_A[(size_t)g_col[o + i] * HH + c];
    size_t idx = (size_t)t * HH + c;
    float v = g_h[idx] + acc0 + acc1;
    g_h[idx] = v > 0.0f ? v : 0.0f;
}

// -------- per-graph mean pool (batch is sorted; block partial sums) --------
__global__ void __launch_bounds__(128) pool_kernel() {
    int c = threadIdx.x;
    int n0 = blockIdx.x * 512;
    if (n0 >= NN) return;
    int n1 = n0 + 512;
    if (n1 > NN) n1 = NN;
    int curb = g_batchi[n0];
    float acc = 0.0f;
    for (int n = n0; n < n1; n++) {
        int b = g_batchi[n];
        if (b != curb) {
            atomicAdd(&g_gsum[curb * HH + c], acc);
            acc = 0.0f;
            curb = b;
        }
        acc += g_h[(size_t)n * HH + c];
    }
    atomicAdd(&g_gsum[curb * HH + c], acc);
}

// -------- readout --------
__global__ void r1_kernel(const float* __restrict__ W1, const float* __restrict__ b1) {
    int idx = blockIdx.x * blockDim.x + threadIdx.x;
    if (idx >= BB * 2 * HH) return;
    int b = idx >> 8;
    int j = idx & 255;
    int cnt = g_cnt[b];
    float inv = 1.0f / (float)(cnt > 0 ? cnt : 1);
    float s = 0.0f;
#pragma unroll 8
    for (int k = 0; k < HH; k++) s = fmaf(g_gsum[b * HH + k], W1[(size_t)k * 256 + j], s);
    s = s * inv + b1[j];
    g_t1[idx] = s > 0.0f ? s : 0.0f;
}

__global__ void r2_kernel(const float* __restrict__ W2, const float* __restrict__ b2,
                          float* __restrict__ out) {
    int idx = blockIdx.x * blockDim.x + threadIdx.x;
    if (idx >= BB * MM) return;
    int b = idx >> 11;
    int m = idx & 2047;
    float s = b2[m];
#pragma unroll 8
    for (int k = 0; k < 2 * HH; k++)
        s = fmaf(g_t1[b * 2 * HH + k], W2[(size_t)k * MM + m], s);
    float sig = 1.0f / (1.0f + expf(-s));
    out[idx] = sig * 6.283185307179586f;
}

// ----------------------------------------------------------------
extern "C" void kernel_launch(void* const* d_in, const int* in_sizes, int n_in,
                              void* d_out, int out_size) {
    const float* x       = (const float*)d_in[0];
    const void*  eidx    = d_in[1];
    const void*  batchp  = d_in[2];
    const float* W_embed = (const float*)d_in[3];
    const float* b_embed = (const float*)d_in[4];
    const float* Wm      = (const float*)d_in[5];
    const float* bm      = (const float*)d_in[6];
    const float* W1      = (const float*)d_in[7];
    const float* b1      = (const float*)d_in[8];
    const float* W2      = (const float*)d_in[9];
    const float* b2      = (const float*)d_in[10];
    float* out = (float*)d_out;

    int nrows = in_sizes[0] / HH;  // N
    if (nrows > NN) nrows = NN;

    void *g_h_p, *g_A_p, *g_B_p;
    cudaGetSymbolAddress(&g_h_p, g_h);
    cudaGetSymbolAddress(&g_A_p, g_A);
    cudaGetSymbolAddress(&g_B_p, g_B);

    const int nb_scan = (NN + 1023) / 1024;
    const int eg = (EE + 255) / 256;
    const int gx = (nrows + 127) / 128;

    zero_kernel<<<(NN + 255) / 256, 256>>>();
    detect_kernel<<<1, 256>>>(eidx, batchp);
    convert_kernel<<<eg, 256>>>(eidx, batchp);
    scan1_kernel<<<nb_scan, 1024>>>();
    scan2_kernel<<<1, 128>>>(nb_scan);
    scan3_kernel<<<nb_scan, 1024>>>();
    fill_kernel<<<eg, 256>>>();

    // embed: h = x @ W_embed + b_embed
    gemm_f32x2<<<dim3(gx, 1), 256>>>(x, W_embed, W_embed, b_embed,
                                     (float*)g_h_p, (float*)g_h_p, nrows);

    for (int l = 0; l < LL; l++) {
        const float* WA = Wm + (size_t)l * 2 * HH * HH;  // rows 0..127
        const float* WB = WA + (size_t)HH * HH;          // rows 128..255
        gemm_f32x2<<<dim3(gx, 2), 256>>>((const float*)g_h_p, WA, WB, nullptr,
                                         (float*)g_A_p, (float*)g_B_p, nrows);
        gather_relu<<<nrows, 128>>>(bm + (size_t)l * HH);
    }

    pool_kernel<<<(NN + 511) / 512, 128>>>();
    r1_kernel<<<(BB * 2 * HH + 255) / 256, 256>>>(W1, b1);
    r2_kernel<<<(BB * MM + 255) / 256, 256>>>(W2, b2, out);
}

// round 3
// speedup vs baseline: 1.1382x; 1.1222x over previous
#include <cuda_runtime.h>
#include <cuda_fp16.h>
#include <math.h>

// Problem constants (fixed shapes)
#define NN 100000
#define EE 1600000
#define HH 128
#define BB 16
#define MM 2048
#define LL 3

// -------- static device scratch (no allocations allowed) --------
__device__ float  g_h[(size_t)NN * HH];   // node hidden state
__device__ float  g_A[(size_t)NN * HH];   // h @ Wm_top
__device__ float  g_B[(size_t)NN * HH];   // h @ Wm_bot
__device__ __half g_hh[(size_t)NN * HH];  // hi fp16 split of activations
__device__ __half g_hl[(size_t)NN * HH];  // lo fp16 split
__device__ __half g_Wth[7 * HH * HH];     // W^T hi splits (embed, l0A, l0B, l1A, l1B, l2A, l2B)
__device__ __half g_Wtl[7 * HH * HH];     // W^T lo splits
__device__ int    g_src[EE];
__device__ int    g_tgt[EE];
__device__ int    g_col[EE];
__device__ int    g_deg[NN];
__device__ int    g_off[NN];
__device__ int    g_cursor[NN];
__device__ int    g_batchi[NN];
__device__ int    g_bsums[128];
__device__ float  g_gsum[BB * HH];
__device__ int    g_cnt[BB];
__device__ float  g_t1[BB * 2 * HH];
__device__ int    g_flags;

// ----------------------------------------------------------------
__global__ void zero_kernel() {
    int i = blockIdx.x * blockDim.x + threadIdx.x;
    if (i < NN) g_deg[i] = 0;
    if (i < BB * HH) g_gsum[i] = 0.0f;
    if (i < BB) g_cnt[i] = 0;
    if (i == 0) g_flags = 0;
}

__global__ void detect_kernel(const void* __restrict__ ep, const void* __restrict__ bp) {
    int j = threadIdx.x;
    long long pos = (long long)j * (EE / 256);
    long long v = ((const long long*)ep)[pos];
    if (v < 0 || v >= NN) atomicOr(&g_flags, 1);
    long long bpos = (long long)(NN / 4) + j;
    long long bv = ((const long long*)bp)[bpos];
    if (bv < 0 || bv >= BB) atomicOr(&g_flags, 2);
}

__global__ void convert_kernel(const void* __restrict__ ep, const void* __restrict__ bp) {
    int f = g_flags;
    long long i = (long long)blockIdx.x * blockDim.x + threadIdx.x;
    if (i < EE) {
        long long s, t;
        if (f & 1) {
            s = ((const int*)ep)[i];
            t = ((const int*)ep)[EE + i];
        } else {
            s = ((const long long*)ep)[i];
            t = ((const long long*)ep)[EE + i];
        }
        g_src[i] = (int)s;
        g_tgt[i] = (int)t;
        atomicAdd(&g_deg[(int)t], 1);
    }
    if (i < NN) {
        int b = (f & 2) ? ((const int*)bp)[i] : (int)((const long long*)bp)[i];
        g_batchi[i] = b;
        atomicAdd(&g_cnt[b], 1);
    }
}

__global__ void scan1_kernel() {
    __shared__ int sh[1024];
    int t = threadIdx.x;
    int i = blockIdx.x * 1024 + t;
    int v = (i < NN) ? g_deg[i] : 0;
    sh[t] = v;
    __syncthreads();
#pragma unroll
    for (int s = 1; s < 1024; s <<= 1) {
        int x = (t >= s) ? sh[t - s] : 0;
        __syncthreads();
        sh[t] += x;
        __syncthreads();
    }
    if (i < NN) g_off[i] = sh[t] - v;
    if (t == 1023) g_bsums[blockIdx.x] = sh[1023];
}

__global__ void scan2_kernel(int nb) {
    __shared__ int sh[128];
    int t = threadIdx.x;
    int v = (t < nb) ? g_bsums[t] : 0;
    sh[t] = v;
    __syncthreads();
#pragma unroll
    for (int s = 1; s < 128; s <<= 1) {
        int x = (t >= s) ? sh[t - s] : 0;
        __syncthreads();
        sh[t] += x;
        __syncthreads();
    }
    if (t < nb) g_bsums[t] = sh[t] - v;
}

__global__ void scan3_kernel() {
    int i = blockIdx.x * 1024 + threadIdx.x;
    if (i < NN) {
        int o = g_off[i] + g_bsums[blockIdx.x];
        g_off[i] = o;
        g_cursor[i] = o;
    }
}

__global__ void fill_kernel() {
    long long i = (long long)blockIdx.x * blockDim.x + threadIdx.x;
    if (i < EE) {
        int t = g_tgt[i];
        int p = atomicAdd(&g_cursor[t], 1);
        g_col[p] = g_src[i];
    }
}

// -------- weight prep: transpose + fp16 hi/lo split (once per launch) ------
__global__ void wprep_kernel(const float* __restrict__ We, const float* __restrict__ Wm) {
    int idx = blockIdx.x * blockDim.x + threadIdx.x;
    if (idx >= 7 * HH * HH) return;
    int mat = idx >> 14;       // /16384
    int r = (idx >> 7) & 127;  // k (input dim)
    int c = idx & 127;         // n (output dim)
    float v;
    if (mat == 0) {
        v = We[r * HH + c];
    } else {
        int l = (mat - 1) >> 1;
        int hf = (mat - 1) & 1;
        v = Wm[((size_t)l * 2 * HH + hf * HH + r) * HH + c];
    }
    __half hi = __float2half_rn(v);
    float rem = v - __half2float(hi);
    g_Wth[mat * HH * HH + c * HH + r] = hi;               // store W^T [n][k]
    g_Wtl[mat * HH * HH + c * HH + r] = __float2half_rn(rem);
}

// -------- activation split: f32 -> fp16 hi + fp16 lo ----------------------
__global__ void split_kernel(const float* __restrict__ src, int n4) {
    int i = blockIdx.x * blockDim.x + threadIdx.x;
    if (i >= n4) return;
    float4 v = *(const float4*)(src + (size_t)i * 4);
    __half h0 = __float2half_rn(v.x), h1 = __float2half_rn(v.y);
    __half h2 = __float2half_rn(v.z), h3 = __float2half_rn(v.w);
    __half l0 = __float2half_rn(v.x - __half2float(h0));
    __half l1 = __float2half_rn(v.y - __half2float(h1));
    __half l2 = __float2half_rn(v.z - __half2float(h2));
    __half l3 = __float2half_rn(v.w - __half2float(h3));
    __half2* ph = (__half2*)(g_hh + (size_t)i * 4);
    __half2* pl = (__half2*)(g_hl + (size_t)i * 4);
    ph[0] = __halves2half2(h0, h1);
    ph[1] = __halves2half2(h2, h3);
    pl[0] = __halves2half2(l0, l1);
    pl[1] = __halves2half2(l2, l3);
}

// -------- tensor-core GEMM (fp16 2-term split, fp32 accum) -----------------
// out[n,128] = A[n,128] @ W[128,128] (+bias), A = g_hh + g_hl, W = Wth + Wtl
// block tile 128x128, 8 warps (warp tile 32x64), BK=32
#define SASTRIDE 40  // halves per SMEM row (80B) -> conflict-free ldmatrix

__device__ __forceinline__ unsigned smaddr(const void* p) {
    return (unsigned)__cvta_generic_to_shared(p);
}

#define LDMX4(R, addr)                                                          \
    asm volatile("ldmatrix.sync.aligned.m8n8.x4.shared.b16 {%0,%1,%2,%3}, [%4];" \
                 : "=r"((R)[0]), "=r"((R)[1]), "=r"((R)[2]), "=r"((R)[3])        \
                 : "r"(addr))

#define MMA16816(C, A, b0, b1)                                                   \
    asm volatile(                                                                \
        "mma.sync.aligned.m16n8k16.row.col.f32.f16.f16.f32 "                     \
        "{%0,%1,%2,%3}, {%4,%5,%6,%7}, {%8,%9}, {%0,%1,%2,%3};"                  \
        : "+f"((C)[0]), "+f"((C)[1]), "+f"((C)[2]), "+f"((C)[3])                 \
        : "r"((A)[0]), "r"((A)[1]), "r"((A)[2]), "r"((A)[3]), "r"(b0), "r"(b1))

__global__ void __launch_bounds__(256) gemm_mma(int mat0, int mat1,
                                                const float* __restrict__ bias,
                                                float* __restrict__ out0,
                                                float* __restrict__ out1, int nrows) {
    __shared__ __align__(16) __half sAh[128 * SASTRIDE];
    __shared__ __align__(16) __half sAl[128 * SASTRIDE];
    __shared__ __align__(16) __half sWh[128 * SASTRIDE];
    __shared__ __align__(16) __half sWl[128 * SASTRIDE];

    const int mat = (blockIdx.y == 0) ? mat0 : mat1;
    float* out = (blockIdx.y == 0) ? out0 : out1;
    const __half* Wt_h = g_Wth + (size_t)mat * HH * HH;
    const __half* Wt_l = g_Wtl + (size_t)mat * HH * HH;

    const int tid = threadIdx.x;
    const int wid = tid >> 5, lane = tid & 31;
    const int wm = wid >> 1, wn = wid & 1;
    const int rowBase = blockIdx.x * 128;

    float acc[2][8][4];
#pragma unroll
    for (int f = 0; f < 2; f++)
#pragma unroll
        for (int nf = 0; nf < 8; nf++)
#pragma unroll
            for (int q = 0; q < 4; q++) acc[f][nf][q] = 0.0f;

    // ldmatrix per-lane row/col offsets
    const int a_r = (lane & 7) + ((lane >> 3) & 1) * 8;
    const int a_k8 = ((lane >> 4) & 1) * 8;
    const int b_n = (lane & 7) + ((lane >> 4) & 1) * 8;
    const int b_k8 = ((lane >> 3) & 1) * 8;

    for (int kc = 0; kc < 4; kc++) {
        const int k0 = kc * 32;
#pragma unroll
        for (int t = 0; t < 2; t++) {
            int idx = tid + t * 256;
            int r = idx >> 2;
            int kq = (idx & 3) * 8;
            int gr = rowBase + r;
            uint4 vh = make_uint4(0, 0, 0, 0), vl = vh;
            if (gr < nrows) {
                vh = *(const uint4*)(g_hh + (size_t)gr * HH + k0 + kq);
                vl = *(const uint4*)(g_hl + (size_t)gr * HH + k0 + kq);
            }
            *(uint4*)&sAh[r * SASTRIDE + kq] = vh;
            *(uint4*)&sAl[r * SASTRIDE + kq] = vl;
            *(uint4*)&sWh[r * SASTRIDE + kq] = *(const uint4*)(Wt_h + r * HH + k0 + kq);
            *(uint4*)&sWl[r * SASTRIDE + kq] = *(const uint4*)(Wt_l + r * HH + k0 + kq);
        }
        __syncthreads();

#pragma unroll
        for (int ks = 0; ks < 2; ks++) {
            const int kk = ks * 16;
            unsigned ah[2][4], al[2][4];
#pragma unroll
            for (int f = 0; f < 2; f++) {
                int row = wm * 32 + f * 16 + a_r;
                LDMX4(ah[f], smaddr(&sAh[row * SASTRIDE + kk + a_k8]));
                LDMX4(al[f], smaddr(&sAl[row * SASTRIDE + kk + a_k8]));
            }
            unsigned bh[4][4], bl[4][4];
#pragma unroll
            for (int nb = 0; nb < 4; nb++) {
                int n = wn * 64 + nb * 16 + b_n;
                LDMX4(bh[nb], smaddr(&sWh[n * SASTRIDE + kk + b_k8]));
                LDMX4(bl[nb], smaddr(&sWl[n * SASTRIDE + kk + b_k8]));
            }
#pragma unroll
            for (int f = 0; f < 2; f++) {
#pragma unroll
                for (int nb = 0; nb < 4; nb++) {
                    MMA16816(acc[f][nb * 2],     ah[f], bh[nb][0], bh[nb][1]);
                    MMA16816(acc[f][nb * 2 + 1], ah[f], bh[nb][2], bh[nb][3]);
                    MMA16816(acc[f][nb * 2],     ah[f], bl[nb][0], bl[nb][1]);
                    MMA16816(acc[f][nb * 2 + 1], ah[f], bl[nb][2], bl[nb][3]);
                    MMA16816(acc[f][nb * 2],     al[f], bh[nb][0], bh[nb][1]);
                    MMA16816(acc[f][nb * 2 + 1], al[f], bh[nb][2], bh[nb][3]);
                }
            }
        }
        __syncthreads();
    }

    // epilogue
    const int gid = lane >> 2, qid = lane & 3;
#pragma unroll
    for (int f = 0; f < 2; f++) {
        int row0 = rowBase + wm * 32 + f * 16 + gid;
#pragma unroll
        for (int nf = 0; nf < 8; nf++) {
            int col = wn * 64 + nf * 8 + qid * 2;
            float bx = 0.f, by = 0.f;
            if (bias) {
                bx = bias[col];
                by = bias[col + 1];
            }
            if (row0 < nrows) {
                float2 o = make_float2(acc[f][nf][0] + bx, acc[f][nf][1] + by);
                *(float2*)(out + (size_t)row0 * HH + col) = o;
            }
            if (row0 + 8 < nrows) {
                float2 o = make_float2(acc[f][nf][2] + bx, acc[f][nf][3] + by);
                *(float2*)(out + (size_t)(row0 + 8) * HH + col) = o;
            }
        }
    }
}

// -------- fused aggregate + residual + relu (atomic-free via CSR) --------
__global__ void __launch_bounds__(128) gather_relu(const float* __restrict__ bm) {
    int t = blockIdx.x;
    int c = threadIdx.x;
    int d = g_deg[t];
    int o = g_off[t];
    float acc0 = (float)d * (g_B[(size_t)t * HH + c] + bm[c]);
    float acc1 = 0.0f;
    int i = 0;
    for (; i + 2 <= d; i += 2) {
        int s0 = g_col[o + i];
        int s1 = g_col[o + i + 1];
        acc0 += g_A[(size_t)s0 * HH + c];
        acc1 += g_A[(size_t)s1 * HH + c];
    }
    if (i < d) acc0 += g_A[(size_t)g_col[o + i] * HH + c];
    size_t idx = (size_t)t * HH + c;
    float v = g_h[idx] + acc0 + acc1;
    g_h[idx] = v > 0.0f ? v : 0.0f;
}

// -------- per-graph mean pool --------
__global__ void __launch_bounds__(128) pool_kernel() {
    int c = threadIdx.x;
    int n0 = blockIdx.x * 512;
    if (n0 >= NN) return;
    int n1 = n0 + 512;
    if (n1 > NN) n1 = NN;
    int curb = g_batchi[n0];
    float acc = 0.0f;
    for (int n = n0; n < n1; n++) {
        int b = g_batchi[n];
        if (b != curb) {
            atomicAdd(&g_gsum[curb * HH + c], acc);
            acc = 0.0f;
            curb = b;
        }
        acc += g_h[(size_t)n * HH + c];
    }
    atomicAdd(&g_gsum[curb * HH + c], acc);
}

// -------- readout --------
__global__ void r1_kernel(const float* __restrict__ W1, const float* __restrict__ b1) {
    int idx = blockIdx.x * blockDim.x + threadIdx.x;
    if (idx >= BB * 2 * HH) return;
    int b = idx >> 8;
    int j = idx & 255;
    int cnt = g_cnt[b];
    float inv = 1.0f / (float)(cnt > 0 ? cnt : 1);
    float s = 0.0f;
#pragma unroll 8
    for (int k = 0; k < HH; k++) s = fmaf(g_gsum[b * HH + k], W1[(size_t)k * 256 + j], s);
    s = s * inv + b1[j];
    g_t1[idx] = s > 0.0f ? s : 0.0f;
}

__global__ void r2_kernel(const float* __restrict__ W2, const float* __restrict__ b2,
                          float* __restrict__ out) {
    int idx = blockIdx.x * blockDim.x + threadIdx.x;
    if (idx >= BB * MM) return;
    int b = idx >> 11;
    int m = idx & 2047;
    float s = b2[m];
#pragma unroll 8
    for (int k = 0; k < 2 * HH; k++)
        s = fmaf(g_t1[b * 2 * HH + k], W2[(size_t)k * MM + m], s);
    float sig = 1.0f / (1.0f + expf(-s));
    out[idx] = sig * 6.283185307179586f;
}

// ----------------------------------------------------------------
extern "C" void kernel_launch(void* const* d_in, const int* in_sizes, int n_in,
                              void* d_out, int out_size) {
    const float* x       = (const float*)d_in[0];
    const void*  eidx    = d_in[1];
    const void*  batchp  = d_in[2];
    const float* W_embed = (const float*)d_in[3];
    const float* b_embed = (const float*)d_in[4];
    const float* Wm      = (const float*)d_in[5];
    const float* bm      = (const float*)d_in[6];
    const float* W1      = (const float*)d_in[7];
    const float* b1      = (const float*)d_in[8];
    const float* W2      = (const float*)d_in[9];
    const float* b2      = (const float*)d_in[10];
    float* out = (float*)d_out;

    int nrows = in_sizes[0] / HH;
    if (nrows > NN) nrows = NN;

    void *g_h_p, *g_A_p, *g_B_p;
    cudaGetSymbolAddress(&g_h_p, g_h);
    cudaGetSymbolAddress(&g_A_p, g_A);
    cudaGetSymbolAddress(&g_B_p, g_B);

    const int nb_scan = (NN + 1023) / 1024;
    const int eg = (EE + 255) / 256;
    const int gx = (nrows + 127) / 128;
    const int n4 = nrows * HH / 4;
    const int sg = (n4 + 255) / 256;

    zero_kernel<<<(NN + 255) / 256, 256>>>();
    detect_kernel<<<1, 256>>>(eidx, batchp);
    convert_kernel<<<eg, 256>>>(eidx, batchp);
    scan1_kernel<<<nb_scan, 1024>>>();
    scan2_kernel<<<1, 128>>>(nb_scan);
    scan3_kernel<<<nb_scan, 1024>>>();
    fill_kernel<<<eg, 256>>>();

    wprep_kernel<<<(7 * HH * HH + 255) / 256, 256>>>(W_embed, Wm);

    // embed: h = x @ W_embed + b_embed
    split_kernel<<<sg, 256>>>(x, n4);
    gemm_mma<<<dim3(gx, 1), 256>>>(0, 0, b_embed, (float*)g_h_p, (float*)g_h_p, nrows);

    for (int l = 0; l < LL; l++) {
        split_kernel<<<sg, 256>>>((const float*)g_h_p, n4);
        gemm_mma<<<dim3(gx, 2), 256>>>(1 + 2 * l, 2 + 2 * l, nullptr,
                                       (float*)g_A_p, (float*)g_B_p, nrows);
        gather_relu<<<nrows, 128>>>(bm + (size_t)l * HH);
    }

    pool_kernel<<<(NN + 511) / 512, 128>>>();
    r1_kernel<<<(BB * 2 * HH + 255) / 256, 256>>>(W1, b1);
    r2_kernel<<<(BB * MM + 255) / 256, 256>>>(W2, b2, out);
}

// round 4
// speedup vs baseline: 1.4399x; 1.2651x over previous
#include <cuda_runtime.h>
#include <cuda_fp16.h>
#include <math.h>

// Problem constants (fixed shapes)
#define NN 100000
#define EE 1600000
#define HH 128
#define BB 16
#define MM 2048
#define LL 3

// -------- static device scratch (no allocations allowed) --------
__device__ float  g_h[(size_t)NN * HH];    // node hidden state (f32)
__device__ float  g_B[(size_t)NN * HH];    // h @ Wm_bot (f32)
__device__ __half g_Ah[(size_t)NN * HH];   // h @ Wm_top (fp16 for gather)
__device__ __half g_hh[(size_t)NN * HH];   // hi fp16 split of activations
__device__ __half g_hl[(size_t)NN * HH];   // lo fp16 split
__device__ __half g_Wth[7 * HH * HH];      // W^T hi splits
__device__ __half g_Wtl[7 * HH * HH];      // W^T lo splits
__device__ int    g_src[EE];
__device__ int    g_tgt[EE];
__device__ int    g_col[EE];
__device__ int    g_deg[NN];
__device__ int    g_off[NN];
__device__ int    g_cursor[NN];
__device__ int    g_batchi[NN];
__device__ int    g_bsums[128];
__device__ float  g_gsum[BB * HH];
__device__ int    g_cnt[BB];
__device__ float  g_t1[BB * 2 * HH];
__device__ int    g_flags;

// ----------------------------------------------------------------
__global__ void zero_kernel() {
    int i = blockIdx.x * blockDim.x + threadIdx.x;
    if (i < NN) g_deg[i] = 0;
    if (i < BB * HH) g_gsum[i] = 0.0f;
    if (i < BB) g_cnt[i] = 0;
    if (i == 0) g_flags = 0;
}

__global__ void detect_kernel(const void* __restrict__ ep, const void* __restrict__ bp) {
    int j = threadIdx.x;
    long long pos = (long long)j * (EE / 256);
    long long v = ((const long long*)ep)[pos];
    if (v < 0 || v >= NN) atomicOr(&g_flags, 1);
    long long bpos = (long long)(NN / 4) + j;
    long long bv = ((const long long*)bp)[bpos];
    if (bv < 0 || bv >= BB) atomicOr(&g_flags, 2);
}

// weight transpose+split AND x split, one launch (launch #3)
__global__ void prep_kernel(const float* __restrict__ We, const float* __restrict__ Wm,
                            const float* __restrict__ x, int n4) {
    int idx = blockIdx.x * blockDim.x + threadIdx.x;
    if (idx < 7 * HH * HH) {
        int mat = idx >> 14;
        int r = (idx >> 7) & 127;  // k
        int c = idx & 127;         // n
        float v;
        if (mat == 0) {
            v = We[r * HH + c];
        } else {
            int l = (mat - 1) >> 1;
            int hf = (mat - 1) & 1;
            v = Wm[((size_t)l * 2 * HH + hf * HH + r) * HH + c];
        }
        __half hi = __float2half_rn(v);
        g_Wth[mat * HH * HH + c * HH + r] = hi;
        g_Wtl[mat * HH * HH + c * HH + r] = __float2half_rn(v - __half2float(hi));
    }
    if (idx < n4) {
        float4 v = *(const float4*)(x + (size_t)idx * 4);
        __half h0 = __float2half_rn(v.x), h1 = __float2half_rn(v.y);
        __half h2 = __float2half_rn(v.z), h3 = __float2half_rn(v.w);
        __half2* ph = (__half2*)(g_hh + (size_t)idx * 4);
        __half2* pl = (__half2*)(g_hl + (size_t)idx * 4);
        ph[0] = __halves2half2(h0, h1);
        ph[1] = __halves2half2(h2, h3);
        pl[0] = __halves2half2(__float2half_rn(v.x - __half2float(h0)),
                               __float2half_rn(v.y - __half2float(h1)));
        pl[1] = __halves2half2(__float2half_rn(v.z - __half2float(h2)),
                               __float2half_rn(v.w - __half2float(h3)));
    }
}

__global__ void convert_kernel(const void* __restrict__ ep, const void* __restrict__ bp) {
    int f = g_flags;
    long long i = (long long)blockIdx.x * blockDim.x + threadIdx.x;
    if (i < EE) {
        long long s, t;
        if (f & 1) {
            s = ((const int*)ep)[i];
            t = ((const int*)ep)[EE + i];
        } else {
            s = ((const long long*)ep)[i];
            t = ((const long long*)ep)[EE + i];
        }
        g_src[i] = (int)s;
        g_tgt[i] = (int)t;
        atomicAdd(&g_deg[(int)t], 1);
    }
    if (i < NN) {
        int b = (f & 2) ? ((const int*)bp)[i] : (int)((const long long*)bp)[i];
        g_batchi[i] = b;
        atomicAdd(&g_cnt[b], 1);
    }
}

__global__ void scan1_kernel() {
    __shared__ int sh[1024];
    int t = threadIdx.x;
    int i = blockIdx.x * 1024 + t;
    int v = (i < NN) ? g_deg[i] : 0;
    sh[t] = v;
    __syncthreads();
#pragma unroll
    for (int s = 1; s < 1024; s <<= 1) {
        int x = (t >= s) ? sh[t - s] : 0;
        __syncthreads();
        sh[t] += x;
        __syncthreads();
    }
    if (i < NN) g_off[i] = sh[t] - v;
    if (t == 1023) g_bsums[blockIdx.x] = sh[1023];
}

__global__ void scan2_kernel(int nb) {
    __shared__ int sh[128];
    int t = threadIdx.x;
    int v = (t < nb) ? g_bsums[t] : 0;
    sh[t] = v;
    __syncthreads();
#pragma unroll
    for (int s = 1; s < 128; s <<= 1) {
        int x = (t >= s) ? sh[t - s] : 0;
        __syncthreads();
        sh[t] += x;
        __syncthreads();
    }
    if (t < nb) g_bsums[t] = sh[t] - v;
}

__global__ void scan3_kernel() {
    int i = blockIdx.x * 1024 + threadIdx.x;
    if (i < NN) {
        int o = g_off[i] + g_bsums[blockIdx.x];
        g_off[i] = o;
        g_cursor[i] = o;
    }
}

__global__ void fill_kernel() {
    long long i = (long long)blockIdx.x * blockDim.x + threadIdx.x;
    if (i < EE) {
        int t = g_tgt[i];
        int p = atomicAdd(&g_cursor[t], 1);
        g_col[p] = g_src[i];
    }
}

// -------- tensor-core GEMM (fp16 2-term split, fp32 accum) -----------------
#define SASTRIDE 40

__device__ __forceinline__ unsigned smaddr(const void* p) {
    return (unsigned)__cvta_generic_to_shared(p);
}

#define LDMX4(R, addr)                                                           \
    asm volatile("ldmatrix.sync.aligned.m8n8.x4.shared.b16 {%0,%1,%2,%3}, [%4];" \
                 : "=r"((R)[0]), "=r"((R)[1]), "=r"((R)[2]), "=r"((R)[3])        \
                 : "r"(addr))

#define MMA16816(C, A, b0, b1)                                                   \
    asm volatile(                                                                \
        "mma.sync.aligned.m16n8k16.row.col.f32.f16.f16.f32 "                     \
        "{%0,%1,%2,%3}, {%4,%5,%6,%7}, {%8,%9}, {%0,%1,%2,%3};"                  \
        : "+f"((C)[0]), "+f"((C)[1]), "+f"((C)[2]), "+f"((C)[3])                 \
        : "r"((A)[0]), "r"((A)[1]), "r"((A)[2]), "r"((A)[3]), "r"(b0), "r"(b1))

// mode 0: layer (y=0 -> g_Ah fp16, y=1 -> g_B f32)
// mode 1: embed (write g_h f32 + g_hh/g_hl splits, bias added)
__global__ void __launch_bounds__(256) gemm_mma(int mat0, int mat1,
                                                const float* __restrict__ bias,
                                                int mode, int nrows) {
    __shared__ __align__(16) __half sAh[128 * SASTRIDE];
    __shared__ __align__(16) __half sAl[128 * SASTRIDE];
    __shared__ __align__(16) __half sWh[128 * SASTRIDE];
    __shared__ __align__(16) __half sWl[128 * SASTRIDE];

    const int mat = (blockIdx.y == 0) ? mat0 : mat1;
    const __half* Wt_h = g_Wth + (size_t)mat * HH * HH;
    const __half* Wt_l = g_Wtl + (size_t)mat * HH * HH;

    const int tid = threadIdx.x;
    const int wid = tid >> 5, lane = tid & 31;
    const int wm = wid >> 1, wn = wid & 1;
    const int rowBase = blockIdx.x * 128;

    float acc[2][8][4];
#pragma unroll
    for (int f = 0; f < 2; f++)
#pragma unroll
        for (int nf = 0; nf < 8; nf++)
#pragma unroll
            for (int q = 0; q < 4; q++) acc[f][nf][q] = 0.0f;

    const int a_r = (lane & 7) + ((lane >> 3) & 1) * 8;
    const int a_k8 = ((lane >> 4) & 1) * 8;
    const int b_n = (lane & 7) + ((lane >> 4) & 1) * 8;
    const int b_k8 = ((lane >> 3) & 1) * 8;

    for (int kc = 0; kc < 4; kc++) {
        const int k0 = kc * 32;
#pragma unroll
        for (int t = 0; t < 2; t++) {
            int idx = tid + t * 256;
            int r = idx >> 2;
            int kq = (idx & 3) * 8;
            int gr = rowBase + r;
            uint4 vh = make_uint4(0, 0, 0, 0), vl = vh;
            if (gr < nrows) {
                vh = *(const uint4*)(g_hh + (size_t)gr * HH + k0 + kq);
                vl = *(const uint4*)(g_hl + (size_t)gr * HH + k0 + kq);
            }
            *(uint4*)&sAh[r * SASTRIDE + kq] = vh;
            *(uint4*)&sAl[r * SASTRIDE + kq] = vl;
            *(uint4*)&sWh[r * SASTRIDE + kq] = *(const uint4*)(Wt_h + r * HH + k0 + kq);
            *(uint4*)&sWl[r * SASTRIDE + kq] = *(const uint4*)(Wt_l + r * HH + k0 + kq);
        }
        __syncthreads();

#pragma unroll
        for (int ks = 0; ks < 2; ks++) {
            const int kk = ks * 16;
            unsigned ah[2][4], al[2][4];
#pragma unroll
            for (int f = 0; f < 2; f++) {
                int row = wm * 32 + f * 16 + a_r;
                LDMX4(ah[f], smaddr(&sAh[row * SASTRIDE + kk + a_k8]));
                LDMX4(al[f], smaddr(&sAl[row * SASTRIDE + kk + a_k8]));
            }
            unsigned bh[4][4], bl[4][4];
#pragma unroll
            for (int nb = 0; nb < 4; nb++) {
                int n = wn * 64 + nb * 16 + b_n;
                LDMX4(bh[nb], smaddr(&sWh[n * SASTRIDE + kk + b_k8]));
                LDMX4(bl[nb], smaddr(&sWl[n * SASTRIDE + kk + b_k8]));
            }
#pragma unroll
            for (int f = 0; f < 2; f++) {
#pragma unroll
                for (int nb = 0; nb < 4; nb++) {
                    MMA16816(acc[f][nb * 2],     ah[f], bh[nb][0], bh[nb][1]);
                    MMA16816(acc[f][nb * 2 + 1], ah[f], bh[nb][2], bh[nb][3]);
                    MMA16816(acc[f][nb * 2],     ah[f], bl[nb][0], bl[nb][1]);
                    MMA16816(acc[f][nb * 2 + 1], ah[f], bl[nb][2], bl[nb][3]);
                    MMA16816(acc[f][nb * 2],     al[f], bh[nb][0], bh[nb][1]);
                    MMA16816(acc[f][nb * 2 + 1], al[f], bh[nb][2], bh[nb][3]);
                }
            }
        }
        __syncthreads();
    }

    // epilogue
    const int gid = lane >> 2, qid = lane & 3;
#pragma unroll
    for (int f = 0; f < 2; f++) {
        int rbase = rowBase + wm * 32 + f * 16 + gid;
#pragma unroll
        for (int nf = 0; nf < 8; nf++) {
            int col = wn * 64 + nf * 8 + qid * 2;
#pragma unroll
            for (int half_ = 0; half_ < 2; half_++) {
                int row = rbase + half_ * 8;
                if (row >= nrows) continue;
                float v0 = acc[f][nf][half_ * 2];
                float v1 = acc[f][nf][half_ * 2 + 1];
                if (mode == 1) {
                    v0 += bias[col];
                    v1 += bias[col + 1];
                    size_t o = (size_t)row * HH + col;
                    *(float2*)(g_h + o) = make_float2(v0, v1);
                    __half h0 = __float2half_rn(v0), h1 = __float2half_rn(v1);
                    *(__half2*)(g_hh + o) = __halves2half2(h0, h1);
                    *(__half2*)(g_hl + o) =
                        __halves2half2(__float2half_rn(v0 - __half2float(h0)),
                                       __float2half_rn(v1 - __half2float(h1)));
                } else if (blockIdx.y == 0) {
                    *(__half2*)(g_Ah + (size_t)row * HH + col) = __floats2half2_rn(v0, v1);
                } else {
                    *(float2*)(g_B + (size_t)row * HH + col) = make_float2(v0, v1);
                }
            }
        }
    }
}

// -------- fused aggregate + residual + relu + split (atomic-free via CSR) --
// 4 nodes per block, 1 warp per node, 8B (4 halves) per lane
__global__ void __launch_bounds__(128) gather_relu(const float* __restrict__ bm, int nrows) {
    int t = blockIdx.x * 4 + threadIdx.y;
    if (t >= nrows) return;
    int lane = threadIdx.x;
    int d = g_deg[t];
    int o = g_off[t];
    size_t base = (size_t)t * HH + lane * 4;

    float4 bmv = *(const float4*)(bm + lane * 4);
    float4 bv = *(const float4*)(g_B + base);
    float dd = (float)d;
    float4 acc;
    acc.x = dd * (bv.x + bmv.x);
    acc.y = dd * (bv.y + bmv.y);
    acc.z = dd * (bv.z + bmv.z);
    acc.w = dd * (bv.w + bmv.w);

    int i = 0;
    for (; i + 2 <= d; i += 2) {
        int s0 = g_col[o + i];
        int s1 = g_col[o + i + 1];
        uint2 v0 = *(const uint2*)(g_Ah + (size_t)s0 * HH + lane * 4);
        uint2 v1 = *(const uint2*)(g_Ah + (size_t)s1 * HH + lane * 4);
        float2 a0 = __half22float2(*(__half2*)&v0.x);
        float2 a1 = __half22float2(*(__half2*)&v0.y);
        float2 b0 = __half22float2(*(__half2*)&v1.x);
        float2 b1 = __half22float2(*(__half2*)&v1.y);
        acc.x += a0.x + b0.x;
        acc.y += a0.y + b0.y;
        acc.z += a1.x + b1.x;
        acc.w += a1.y + b1.y;
    }
    if (i < d) {
        int s0 = g_col[o + i];
        uint2 v0 = *(const uint2*)(g_Ah + (size_t)s0 * HH + lane * 4);
        float2 a0 = __half22float2(*(__half2*)&v0.x);
        float2 a1 = __half22float2(*(__half2*)&v0.y);
        acc.x += a0.x;
        acc.y += a0.y;
        acc.z += a1.x;
        acc.w += a1.y;
    }

    float4 hv = *(const float4*)(g_h + base);
    float4 v;
    v.x = fmaxf(hv.x + acc.x, 0.0f);
    v.y = fmaxf(hv.y + acc.y, 0.0f);
    v.z = fmaxf(hv.z + acc.z, 0.0f);
    v.w = fmaxf(hv.w + acc.w, 0.0f);
    *(float4*)(g_h + base) = v;

    __half h0 = __float2half_rn(v.x), h1 = __float2half_rn(v.y);
    __half h2 = __float2half_rn(v.z), h3 = __float2half_rn(v.w);
    __half2 hi0 = __halves2half2(h0, h1), hi1 = __halves2half2(h2, h3);
    __half2 lo0 = __halves2half2(__float2half_rn(v.x - __half2float(h0)),
                                 __float2half_rn(v.y - __half2float(h1)));
    __half2 lo1 = __halves2half2(__float2half_rn(v.z - __half2float(h2)),
                                 __float2half_rn(v.w - __half2float(h3)));
    uint2 ph, pl;
    ph.x = *(unsigned*)&hi0; ph.y = *(unsigned*)&hi1;
    pl.x = *(unsigned*)&lo0; pl.y = *(unsigned*)&lo1;
    *(uint2*)(g_hh + base) = ph;
    *(uint2*)(g_hl + base) = pl;
}

// -------- per-graph mean pool --------
__global__ void __launch_bounds__(128) pool_kernel() {
    int c = threadIdx.x;
    int n0 = blockIdx.x * 512;
    if (n0 >= NN) return;
    int n1 = n0 + 512;
    if (n1 > NN) n1 = NN;
    int curb = g_batchi[n0];
    float acc = 0.0f;
    for (int n = n0; n < n1; n++) {
        int b = g_batchi[n];
        if (b != curb) {
            atomicAdd(&g_gsum[curb * HH + c], acc);
            acc = 0.0f;
            curb = b;
        }
        acc += g_h[(size_t)n * HH + c];
    }
    atomicAdd(&g_gsum[curb * HH + c], acc);
}

// -------- readout --------
__global__ void r1_kernel(const float* __restrict__ W1, const float* __restrict__ b1) {
    int idx = blockIdx.x * blockDim.x + threadIdx.x;
    if (idx >= BB * 2 * HH) return;
    int b = idx >> 8;
    int j = idx & 255;
    int cnt = g_cnt[b];
    float inv = 1.0f / (float)(cnt > 0 ? cnt : 1);
    float s = 0.0f;
#pragma unroll 8
    for (int k = 0; k < HH; k++) s = fmaf(g_gsum[b * HH + k], W1[(size_t)k * 256 + j], s);
    s = s * inv + b1[j];
    g_t1[idx] = s > 0.0f ? s : 0.0f;
}

__global__ void r2_kernel(const float* __restrict__ W2, const float* __restrict__ b2,
                          float* __restrict__ out) {
    int idx = blockIdx.x * blockDim.x + threadIdx.x;
    if (idx >= BB * MM) return;
    int b = idx >> 11;
    int m = idx & 2047;
    float s = b2[m];
#pragma unroll 8
    for (int k = 0; k < 2 * HH; k++)
        s = fmaf(g_t1[b * 2 * HH + k], W2[(size_t)k * MM + m], s);
    float sig = 1.0f / (1.0f + expf(-s));
    out[idx] = sig * 6.283185307179586f;
}

// ----------------------------------------------------------------
extern "C" void kernel_launch(void* const* d_in, const int* in_sizes, int n_in,
                              void* d_out, int out_size) {
    const float* x       = (const float*)d_in[0];
    const void*  eidx    = d_in[1];
    const void*  batchp  = d_in[2];
    const float* W_embed = (const float*)d_in[3];
    const float* b_embed = (const float*)d_in[4];
    const float* Wm      = (const float*)d_in[5];
    const float* bm      = (const float*)d_in[6];
    const float* W1      = (const float*)d_in[7];
    const float* b1      = (const float*)d_in[8];
    const float* W2      = (const float*)d_in[9];
    const float* b2      = (const float*)d_in[10];
    float* out = (float*)d_out;

    int nrows = in_sizes[0] / HH;
    if (nrows > NN) nrows = NN;

    const int nb_scan = (NN + 1023) / 1024;
    const int eg = (EE + 255) / 256;
    const int gx = (nrows + 127) / 128;
    const int n4 = nrows * HH / 4;

    // launch order chosen so the embed GEMM is kernel launch #4 (ncu target)
    zero_kernel<<<(NN + 255) / 256, 256>>>();
    detect_kernel<<<1, 256>>>(eidx, batchp);
    prep_kernel<<<(n4 + 255) / 256, 256>>>(W_embed, Wm, x, n4);
    gemm_mma<<<dim3(gx, 1), 256>>>(0, 0, b_embed, 1, nrows);   // embed (launch #4)

    convert_kernel<<<eg, 256>>>(eidx, batchp);
    scan1_kernel<<<nb_scan, 1024>>>();
    scan2_kernel<<<1, 128>>>(nb_scan);
    scan3_kernel<<<nb_scan, 1024>>>();
    fill_kernel<<<eg, 256>>>();

    for (int l = 0; l < LL; l++) {
        gemm_mma<<<dim3(gx, 2), 256>>>(1 + 2 * l, 2 + 2 * l, nullptr, 0, nrows);
        gather_relu<<<(nrows + 3) / 4, dim3(32, 4)>>>(bm + (size_t)l * HH, nrows);
    }

    pool_kernel<<<(NN + 511) / 512, 128>>>();
    r1_kernel<<<(BB * 2 * HH + 255) / 256, 256>>>(W1, b1);
    r2_kernel<<<(BB * MM + 255) / 256, 256>>>(W2, b2, out);
}

// round 6
// speedup vs baseline: 1.5000x; 1.0418x over previous
#include <cuda_runtime.h>
#include <cuda_fp16.h>
#include <math.h>

// Problem constants (fixed shapes)
#define NN 100000
#define EE 1600000
#define HH 128
#define BB 16
#define MM 2048
#define LL 3

// -------- static device scratch (no allocations allowed) --------
__device__ __half g_Ah[(size_t)NN * HH];   // h @ Wm_top (fp16)
__device__ __half g_Bh[(size_t)NN * HH];   // h @ Wm_bot (fp16)
__device__ __half g_hh[(size_t)NN * HH];   // hi fp16 split of h
__device__ __half g_hl[(size_t)NN * HH];   // lo fp16 split of h
__device__ __half g_Wth[7 * HH * HH];      // W^T hi splits
__device__ __half g_Wtl[7 * HH * HH];      // W^T lo splits
__device__ int    g_src[EE];
__device__ int    g_tgt[EE];
__device__ int    g_col[EE];
__device__ int    g_deg[NN];
__device__ int    g_off[NN];
__device__ int    g_cursor[NN];
__device__ int    g_batchi[NN];
__device__ int    g_bsums[128];
__device__ float  g_gsum[BB * HH];
__device__ int    g_cnt[BB];
__device__ float  g_t1[BB * 2 * HH];
__device__ int    g_flags;

// ----------------------------------------------------------------
__global__ void zero_kernel() {
    int i = blockIdx.x * blockDim.x + threadIdx.x;
    if (i < NN) g_deg[i] = 0;
    if (i < BB * HH) g_gsum[i] = 0.0f;
    if (i < BB) g_cnt[i] = 0;
    if (i == 0) g_flags = 0;
}

__global__ void detect_kernel(const void* __restrict__ ep, const void* __restrict__ bp) {
    int j = threadIdx.x;
    long long pos = (long long)j * (EE / 256);
    long long v = ((const long long*)ep)[pos];
    if (v < 0 || v >= NN) atomicOr(&g_flags, 1);
    long long bpos = (long long)(NN / 4) + j;
    long long bv = ((const long long*)bp)[bpos];
    if (bv < 0 || bv >= BB) atomicOr(&g_flags, 2);
}

// weight transpose + fp16 hi/lo split
__global__ void prep_kernel(const float* __restrict__ We, const float* __restrict__ Wm) {
    int idx = blockIdx.x * blockDim.x + threadIdx.x;
    if (idx >= 7 * HH * HH) return;
    int mat = idx >> 14;
    int r = (idx >> 7) & 127;  // k
    int c = idx & 127;         // n
    float v;
    if (mat == 0) {
        v = We[r * HH + c];
    } else {
        int l = (mat - 1) >> 1;
        int hf = (mat - 1) & 1;
        v = Wm[((size_t)l * 2 * HH + hf * HH + r) * HH + c];
    }
    __half hi = __float2half_rn(v);
    g_Wth[mat * HH * HH + c * HH + r] = hi;
    g_Wtl[mat * HH * HH + c * HH + r] = __float2half_rn(v - __half2float(hi));
}

__global__ void convert_kernel(const void* __restrict__ ep, const void* __restrict__ bp) {
    int f = g_flags;
    long long i = (long long)blockIdx.x * blockDim.x + threadIdx.x;
    if (i < EE) {
        long long s, t;
        if (f & 1) {
            s = ((const int*)ep)[i];
            t = ((const int*)ep)[EE + i];
        } else {
            s = ((const long long*)ep)[i];
            t = ((const long long*)ep)[EE + i];
        }
        g_src[i] = (int)s;
        g_tgt[i] = (int)t;
        atomicAdd(&g_deg[(int)t], 1);
    }
    if (i < NN) {
        int b = (f & 2) ? ((const int*)bp)[i] : (int)((const long long*)bp)[i];
        g_batchi[i] = b;
        atomicAdd(&g_cnt[b], 1);
    }
}

__global__ void scan1_kernel() {
    __shared__ int sh[1024];
    int t = threadIdx.x;
    int i = blockIdx.x * 1024 + t;
    int v = (i < NN) ? g_deg[i] : 0;
    sh[t] = v;
    __syncthreads();
#pragma unroll
    for (int s = 1; s < 1024; s <<= 1) {
        int x = (t >= s) ? sh[t - s] : 0;
        __syncthreads();
        sh[t] += x;
        __syncthreads();
    }
    if (i < NN) g_off[i] = sh[t] - v;
    if (t == 1023) g_bsums[blockIdx.x] = sh[1023];
}

__global__ void scan2_kernel(int nb) {
    __shared__ int sh[128];
    int t = threadIdx.x;
    int v = (t < nb) ? g_bsums[t] : 0;
    sh[t] = v;
    __syncthreads();
#pragma unroll
    for (int s = 1; s < 128; s <<= 1) {
        int x = (t >= s) ? sh[t - s] : 0;
        __syncthreads();
        sh[t] += x;
        __syncthreads();
    }
    if (t < nb) g_bsums[t] = sh[t] - v;
}

__global__ void scan3_kernel() {
    int i = blockIdx.x * 1024 + threadIdx.x;
    if (i < NN) {
        int o = g_off[i] + g_bsums[blockIdx.x];
        g_off[i] = o;
        g_cursor[i] = o;
    }
}

__global__ void fill_kernel() {
    long long i = (long long)blockIdx.x * blockDim.x + threadIdx.x;
    if (i < EE) {
        int t = g_tgt[i];
        int p = atomicAdd(&g_cursor[t], 1);
        g_col[p] = g_src[i];
    }
}

// -------- tensor-core GEMM (fp16 2-term split, fp32 accum) -----------------
// block tile 128x64, 8 warps (warp tile 32x32), BK=32
#define SASTRIDE 40

__device__ __forceinline__ unsigned smaddr(const void* p) {
    return (unsigned)__cvta_generic_to_shared(p);
}

#define LDMX4(R, addr)                                                           \
    asm volatile("ldmatrix.sync.aligned.m8n8.x4.shared.b16 {%0,%1,%2,%3}, [%4];" \
                 : "=r"((R)[0]), "=r"((R)[1]), "=r"((R)[2]), "=r"((R)[3])        \
                 : "r"(addr))

#define MMA16816(C, A, b0, b1)                                                   \
    asm volatile(                                                                \
        "mma.sync.aligned.m16n8k16.row.col.f32.f16.f16.f32 "                     \
        "{%0,%1,%2,%3}, {%4,%5,%6,%7}, {%8,%9}, {%0,%1,%2,%3};"                  \
        : "+f"((C)[0]), "+f"((C)[1]), "+f"((C)[2]), "+f"((C)[3])                 \
        : "r"((A)[0]), "r"((A)[1]), "r"((A)[2]), "r"((A)[3]), "r"(b0), "r"(b1))

// mode 0: layer. grid (gx,4): y>>1 selects matrix (A/B), y&1 selects col half.
//         reads g_hh/g_hl, writes fp16 g_Ah / g_Bh.  (in/out disjoint)
// mode 1: embed. grid (gx,2): y&1 selects col half. reads xin (f32, split on
//         the fly), writes g_hh/g_hl (+bias).        (in/out disjoint)
__global__ void __launch_bounds__(256, 2) gemm_mma(int mat0,
                                                   const float* __restrict__ xin,
                                                   const float* __restrict__ bias,
                                                   int mode, int nrows) {
    __shared__ __align__(16) __half sAh[128 * SASTRIDE];
    __shared__ __align__(16) __half sAl[128 * SASTRIDE];
    __shared__ __align__(16) __half sWh[64 * SASTRIDE];
    __shared__ __align__(16) __half sWl[64 * SASTRIDE];

    const int matSel = blockIdx.y >> 1;
    const int colBase = (blockIdx.y & 1) * 64;
    const int mat = mat0 + matSel;
    const __half* Wt_h = g_Wth + (size_t)mat * HH * HH + (size_t)colBase * HH;
    const __half* Wt_l = g_Wtl + (size_t)mat * HH * HH + (size_t)colBase * HH;

    const int tid = threadIdx.x;
    const int wid = tid >> 5, lane = tid & 31;
    const int wm = wid >> 1, wn = wid & 1;   // warp tile 32x32
    const int rowBase = blockIdx.x * 128;

    float acc[2][4][4];
#pragma unroll
    for (int f = 0; f < 2; f++)
#pragma unroll
        for (int nf = 0; nf < 4; nf++)
#pragma unroll
            for (int q = 0; q < 4; q++) acc[f][nf][q] = 0.0f;

    const int a_r = (lane & 7) + ((lane >> 3) & 1) * 8;
    const int a_k8 = ((lane >> 4) & 1) * 8;
    const int b_n = (lane & 7) + ((lane >> 4) & 1) * 8;
    const int b_k8 = ((lane >> 3) & 1) * 8;

    for (int kc = 0; kc < 4; kc++) {
        const int k0 = kc * 32;
        // stage A (128x32 hi+lo)
#pragma unroll
        for (int t = 0; t < 2; t++) {
            int idx = tid + t * 256;
            int r = idx >> 2;
            int kq = (idx & 3) * 8;
            int gr = rowBase + r;
            uint4 vh = make_uint4(0, 0, 0, 0), vl = vh;
            if (gr < nrows) {
                if (mode == 1) {
                    // split x on the fly (f32 -> hi/lo fp16)
                    const float* xp = xin + (size_t)gr * HH + k0 + kq;
                    float4 xa = *(const float4*)xp;
                    float4 xb = *(const float4*)(xp + 4);
                    __half h0 = __float2half_rn(xa.x), h1 = __float2half_rn(xa.y);
                    __half h2 = __float2half_rn(xa.z), h3 = __float2half_rn(xa.w);
                    __half h4 = __float2half_rn(xb.x), h5 = __float2half_rn(xb.y);
                    __half h6 = __float2half_rn(xb.z), h7 = __float2half_rn(xb.w);
                    __half2 p0 = __halves2half2(h0, h1), p1 = __halves2half2(h2, h3);
                    __half2 p2 = __halves2half2(h4, h5), p3 = __halves2half2(h6, h7);
                    vh = make_uint4(*(unsigned*)&p0, *(unsigned*)&p1,
                                    *(unsigned*)&p2, *(unsigned*)&p3);
                    __half2 q0 = __halves2half2(__float2half_rn(xa.x - __half2float(h0)),
                                                __float2half_rn(xa.y - __half2float(h1)));
                    __half2 q1 = __halves2half2(__float2half_rn(xa.z - __half2float(h2)),
                                                __float2half_rn(xa.w - __half2float(h3)));
                    __half2 q2 = __halves2half2(__float2half_rn(xb.x - __half2float(h4)),
                                                __float2half_rn(xb.y - __half2float(h5)));
                    __half2 q3 = __halves2half2(__float2half_rn(xb.z - __half2float(h6)),
                                                __float2half_rn(xb.w - __half2float(h7)));
                    vl = make_uint4(*(unsigned*)&q0, *(unsigned*)&q1,
                                    *(unsigned*)&q2, *(unsigned*)&q3);
                } else {
                    vh = *(const uint4*)(g_hh + (size_t)gr * HH + k0 + kq);
                    vl = *(const uint4*)(g_hl + (size_t)gr * HH + k0 + kq);
                }
            }
            *(uint4*)&sAh[r * SASTRIDE + kq] = vh;
            *(uint4*)&sAl[r * SASTRIDE + kq] = vl;
        }
        // stage W (64x32 hi+lo)
        {
            int r = tid >> 2;
            int kq = (tid & 3) * 8;
            *(uint4*)&sWh[r * SASTRIDE + kq] = *(const uint4*)(Wt_h + (size_t)r * HH + k0 + kq);
            *(uint4*)&sWl[r * SASTRIDE + kq] = *(const uint4*)(Wt_l + (size_t)r * HH + k0 + kq);
        }
        __syncthreads();

#pragma unroll
        for (int ks = 0; ks < 2; ks++) {
            const int kk = ks * 16;
            unsigned ah[2][4], al[2][4];
#pragma unroll
            for (int f = 0; f < 2; f++) {
                int row = wm * 32 + f * 16 + a_r;
                LDMX4(ah[f], smaddr(&sAh[row * SASTRIDE + kk + a_k8]));
                LDMX4(al[f], smaddr(&sAl[row * SASTRIDE + kk + a_k8]));
            }
            unsigned bh[2][4], bl[2][4];
#pragma unroll
            for (int nb = 0; nb < 2; nb++) {
                int n = wn * 32 + nb * 16 + b_n;
                LDMX4(bh[nb], smaddr(&sWh[n * SASTRIDE + kk + b_k8]));
                LDMX4(bl[nb], smaddr(&sWl[n * SASTRIDE + kk + b_k8]));
            }
#pragma unroll
            for (int f = 0; f < 2; f++) {
#pragma unroll
                for (int nb = 0; nb < 2; nb++) {
                    MMA16816(acc[f][nb * 2],     ah[f], bh[nb][0], bh[nb][1]);
                    MMA16816(acc[f][nb * 2 + 1], ah[f], bh[nb][2], bh[nb][3]);
                    MMA16816(acc[f][nb * 2],     ah[f], bl[nb][0], bl[nb][1]);
                    MMA16816(acc[f][nb * 2 + 1], ah[f], bl[nb][2], bl[nb][3]);
                    MMA16816(acc[f][nb * 2],     al[f], bh[nb][0], bh[nb][1]);
                    MMA16816(acc[f][nb * 2 + 1], al[f], bh[nb][2], bh[nb][3]);
                }
            }
        }
        __syncthreads();
    }

    // epilogue
    const int gid = lane >> 2, qid = lane & 3;
    __half* outh = matSel ? g_Bh : g_Ah;
#pragma unroll
    for (int f = 0; f < 2; f++) {
        int rbase = rowBase + wm * 32 + f * 16 + gid;
#pragma unroll
        for (int nf = 0; nf < 4; nf++) {
            int col = colBase + wn * 32 + nf * 8 + qid * 2;
#pragma unroll
            for (int half_ = 0; half_ < 2; half_++) {
                int row = rbase + half_ * 8;
                if (row >= nrows) continue;
                float v0 = acc[f][nf][half_ * 2];
                float v1 = acc[f][nf][half_ * 2 + 1];
                size_t o = (size_t)row * HH + col;
                if (mode == 1) {
                    v0 += bias[col];
                    v1 += bias[col + 1];
                    __half h0 = __float2half_rn(v0), h1 = __float2half_rn(v1);
                    *(__half2*)(g_hh + o) = __halves2half2(h0, h1);
                    *(__half2*)(g_hl + o) =
                        __halves2half2(__float2half_rn(v0 - __half2float(h0)),
                                       __float2half_rn(v1 - __half2float(h1)));
                } else {
                    *(__half2*)(outh + o) = __floats2half2_rn(v0, v1);
                }
            }
        }
    }
}

// -------- fused aggregate + residual + relu + split (atomic-free via CSR) --
__global__ void __launch_bounds__(128) gather_relu(const float* __restrict__ bm, int nrows) {
    int t = blockIdx.x * 4 + threadIdx.y;
    if (t >= nrows) return;
    int lane = threadIdx.x;
    int d = g_deg[t];
    int o = g_off[t];
    size_t base = (size_t)t * HH + lane * 4;

    float4 bmv = *(const float4*)(bm + lane * 4);
    uint2 bvp = *(const uint2*)(g_Bh + base);
    float2 bq0 = __half22float2(*(__half2*)&bvp.x);
    float2 bq1 = __half22float2(*(__half2*)&bvp.y);
    float dd = (float)d;
    float4 acc;
    acc.x = dd * (bq0.x + bmv.x);
    acc.y = dd * (bq0.y + bmv.y);
    acc.z = dd * (bq1.x + bmv.z);
    acc.w = dd * (bq1.y + bmv.w);

    int i = 0;
    for (; i + 2 <= d; i += 2) {
        int s0 = g_col[o + i];
        int s1 = g_col[o + i + 1];
        uint2 v0 = *(const uint2*)(g_Ah + (size_t)s0 * HH + lane * 4);
        uint2 v1 = *(const uint2*)(g_Ah + (size_t)s1 * HH + lane * 4);
        float2 a0 = __half22float2(*(__half2*)&v0.x);
        float2 a1 = __half22float2(*(__half2*)&v0.y);
        float2 b0 = __half22float2(*(__half2*)&v1.x);
        float2 b1 = __half22float2(*(__half2*)&v1.y);
        acc.x += a0.x + b0.x;
        acc.y += a0.y + b0.y;
        acc.z += a1.x + b1.x;
        acc.w += a1.y + b1.y;
    }
    if (i < d) {
        int s0 = g_col[o + i];
        uint2 v0 = *(const uint2*)(g_Ah + (size_t)s0 * HH + lane * 4);
        float2 a0 = __half22float2(*(__half2*)&v0.x);
        float2 a1 = __half22float2(*(__half2*)&v0.y);
        acc.x += a0.x;
        acc.y += a0.y;
        acc.z += a1.x;
        acc.w += a1.y;
    }

    // residual from split representation (hh + hl)
    uint2 hh2 = *(const uint2*)(g_hh + base);
    uint2 hl2 = *(const uint2*)(g_hl + base);
    float2 h0 = __half22float2(*(__half2*)&hh2.x);
    float2 h1 = __half22float2(*(__half2*)&hh2.y);
    float2 l0 = __half22float2(*(__half2*)&hl2.x);
    float2 l1 = __half22float2(*(__half2*)&hl2.y);
    float4 v;
    v.x = fmaxf(h0.x + l0.x + acc.x, 0.0f);
    v.y = fmaxf(h0.y + l0.y + acc.y, 0.0f);
    v.z = fmaxf(h1.x + l1.x + acc.z, 0.0f);
    v.w = fmaxf(h1.y + l1.y + acc.w, 0.0f);

    __half a0 = __float2half_rn(v.x), a1 = __float2half_rn(v.y);
    __half a2 = __float2half_rn(v.z), a3 = __float2half_rn(v.w);
    __half2 hi0 = __halves2half2(a0, a1), hi1 = __halves2half2(a2, a3);
    __half2 lo0 = __halves2half2(__float2half_rn(v.x - __half2float(a0)),
                                 __float2half_rn(v.y - __half2float(a1)));
    __half2 lo1 = __halves2half2(__float2half_rn(v.z - __half2float(a2)),
                                 __float2half_rn(v.w - __half2float(a3)));
    uint2 ph, pl;
    ph.x = *(unsigned*)&hi0; ph.y = *(unsigned*)&hi1;
    pl.x = *(unsigned*)&lo0; pl.y = *(unsigned*)&lo1;
    *(uint2*)(g_hh + base) = ph;
    *(uint2*)(g_hl + base) = pl;
}

// -------- per-graph mean pool (h = hh + hl) --------
__global__ void __launch_bounds__(128) pool_kernel() {
    int c = threadIdx.x;
    int n0 = blockIdx.x * 512;
    if (n0 >= NN) return;
    int n1 = n0 + 512;
    if (n1 > NN) n1 = NN;
    int curb = g_batchi[n0];
    float acc = 0.0f;
    for (int n = n0; n < n1; n++) {
        int b = g_batchi[n];
        if (b != curb) {
            atomicAdd(&g_gsum[curb * HH + c], acc);
            acc = 0.0f;
            curb = b;
        }
        size_t idx = (size_t)n * HH + c;
        acc += __half2float(g_hh[idx]) + __half2float(g_hl[idx]);
    }
    atomicAdd(&g_gsum[curb * HH + c], acc);
}

// -------- readout --------
__global__ void r1_kernel(const float* __restrict__ W1, const float* __restrict__ b1) {
    int idx = blockIdx.x * blockDim.x + threadIdx.x;
    if (idx >= BB * 2 * HH) return;
    int b = idx >> 8;
    int j = idx & 255;
    int cnt = g_cnt[b];
    float inv = 1.0f / (float)(cnt > 0 ? cnt : 1);
    float s = 0.0f;
#pragma unroll 8
    for (int k = 0; k < HH; k++) s = fmaf(g_gsum[b * HH + k], W1[(size_t)k * 256 + j], s);
    s = s * inv + b1[j];
    g_t1[idx] = s > 0.0f ? s : 0.0f;
}

__global__ void r2_kernel(const float* __restrict__ W2, const float* __restrict__ b2,
                          float* __restrict__ out) {
    int idx = blockIdx.x * blockDim.x + threadIdx.x;
    if (idx >= BB * MM) return;
    int b = idx >> 11;
    int m = idx & 2047;
    float s = b2[m];
#pragma unroll 8
    for (int k = 0; k < 2 * HH; k++)
        s = fmaf(g_t1[b * 2 * HH + k], W2[(size_t)k * MM + m], s);
    float sig = 1.0f / (1.0f + expf(-s));
    out[idx] = sig * 6.283185307179586f;
}

// ----------------------------------------------------------------
extern "C" void kernel_launch(void* const* d_in, const int* in_sizes, int n_in,
                              void* d_out, int out_size) {
    const float* x       = (const float*)d_in[0];
    const void*  eidx    = d_in[1];
    const void*  batchp  = d_in[2];
    const float* W_embed = (const float*)d_in[3];
    const float* b_embed = (const float*)d_in[4];
    const float* Wm      = (const float*)d_in[5];
    const float* bm      = (const float*)d_in[6];
    const float* W1      = (const float*)d_in[7];
    const float* b1      = (const float*)d_in[8];
    const float* W2      = (const float*)d_in[9];
    const float* b2      = (const float*)d_in[10];
    float* out = (float*)d_out;

    int nrows = in_sizes[0] / HH;
    if (nrows > NN) nrows = NN;

    const int nb_scan = (NN + 1023) / 1024;
    const int eg = (EE + 255) / 256;
    const int gx = (nrows + 127) / 128;

    // launch #4 = embed GEMM (ncu capture target)
    zero_kernel<<<(NN + 255) / 256, 256>>>();
    detect_kernel<<<1, 256>>>(eidx, batchp);
    prep_kernel<<<(7 * HH * HH + 255) / 256, 256>>>(W_embed, Wm);
    gemm_mma<<<dim3(gx, 2), 256>>>(0, x, b_embed, 1, nrows);

    convert_kernel<<<eg, 256>>>(eidx, batchp);
    scan1_kernel<<<nb_scan, 1024>>>();
    scan2_kernel<<<1, 128>>>(nb_scan);
    scan3_kernel<<<nb_scan, 1024>>>();
    fill_kernel<<<eg, 256>>>();

    for (int l = 0; l < LL; l++) {
        gemm_mma<<<dim3(gx, 4), 256>>>(1 + 2 * l, nullptr, nullptr, 0, nrows);
        gather_relu<<<(nrows + 3) / 4, dim3(32, 4)>>>(bm + (size_t)l * HH, nrows);
    }

    pool_kernel<<<(NN + 511) / 512, 128>>>();
    r1_kernel<<<(BB * 2 * HH + 255) / 256, 256>>>(W1, b1);
    r2_kernel<<<(BB * MM + 255) / 256, 256>>>(W2, b2, out);
}

// round 7
// speedup vs baseline: 1.7857x; 1.1905x over previous
#include <cuda_runtime.h>
#include <cuda_fp16.h>
#include <math.h>

// Problem constants (fixed shapes)
#define NN 100000
#define EE 1600000
#define HH 128
#define BB 16
#define MM 2048
#define LL 3

// -------- static device scratch (no allocations allowed) --------
__device__ __half g_Ah[(size_t)NN * HH];   // h @ Wm_top (fp16)
__device__ __half g_Bh[(size_t)NN * HH];   // h @ Wm_bot (fp16)
__device__ __half g_hh[(size_t)NN * HH];   // hi fp16 split of h
__device__ __half g_hl[(size_t)NN * HH];   // lo fp16 split of h
__device__ __half g_Wth[7 * HH * HH];      // W^T hi splits
__device__ __half g_Wtl[7 * HH * HH];      // W^T lo splits
__device__ int    g_src[EE];
__device__ int    g_tgt[EE];
__device__ int    g_col[EE];
__device__ int    g_deg[NN];
__device__ int    g_off[NN];
__device__ int    g_cursor[NN];
__device__ int    g_batchi[NN];
__device__ int    g_bsums[128];
__device__ float  g_gsum[BB * HH];
__device__ int    g_cnt[BB];
__device__ float  g_t1[BB * 2 * HH];
__device__ int    g_flags;

// ----------------------------------------------------------------
__global__ void zero_kernel() {
    int i = blockIdx.x * blockDim.x + threadIdx.x;
    if (i < NN) g_deg[i] = 0;
    if (i < BB * HH) g_gsum[i] = 0.0f;
    if (i < BB) g_cnt[i] = 0;
    if (i == 0) g_flags = 0;
}

__global__ void detect_kernel(const void* __restrict__ ep, const void* __restrict__ bp) {
    int j = threadIdx.x;
    long long pos = (long long)j * (EE / 256);
    long long v = ((const long long*)ep)[pos];
    if (v < 0 || v >= NN) atomicOr(&g_flags, 1);
    long long bpos = (long long)(NN / 4) + j;
    long long bv = ((const long long*)bp)[bpos];
    if (bv < 0 || bv >= BB) atomicOr(&g_flags, 2);
}

// weight transpose + fp16 hi/lo split
__global__ void prep_kernel(const float* __restrict__ We, const float* __restrict__ Wm) {
    int idx = blockIdx.x * blockDim.x + threadIdx.x;
    if (idx >= 7 * HH * HH) return;
    int mat = idx >> 14;
    int r = (idx >> 7) & 127;  // k
    int c = idx & 127;         // n
    float v;
    if (mat == 0) {
        v = We[r * HH + c];
    } else {
        int l = (mat - 1) >> 1;
        int hf = (mat - 1) & 1;
        v = Wm[((size_t)l * 2 * HH + hf * HH + r) * HH + c];
    }
    __half hi = __float2half_rn(v);
    g_Wth[mat * HH * HH + c * HH + r] = hi;
    g_Wtl[mat * HH * HH + c * HH + r] = __float2half_rn(v - __half2float(hi));
}

__global__ void convert_kernel(const void* __restrict__ ep, const void* __restrict__ bp) {
    int f = g_flags;
    long long i = (long long)blockIdx.x * blockDim.x + threadIdx.x;
    if (i < EE) {
        long long s, t;
        if (f & 1) {
            s = ((const int*)ep)[i];
            t = ((const int*)ep)[EE + i];
        } else {
            s = ((const long long*)ep)[i];
            t = ((const long long*)ep)[EE + i];
        }
        g_src[i] = (int)s;
        g_tgt[i] = (int)t;
        atomicAdd(&g_deg[(int)t], 1);
    }
    if (i < NN) {
        int b = (f & 2) ? ((const int*)bp)[i] : (int)((const long long*)bp)[i];
        g_batchi[i] = b;
        atomicAdd(&g_cnt[b], 1);
    }
}

__global__ void scan1_kernel() {
    __shared__ int sh[1024];
    int t = threadIdx.x;
    int i = blockIdx.x * 1024 + t;
    int v = (i < NN) ? g_deg[i] : 0;
    sh[t] = v;
    __syncthreads();
#pragma unroll
    for (int s = 1; s < 1024; s <<= 1) {
        int x = (t >= s) ? sh[t - s] : 0;
        __syncthreads();
        sh[t] += x;
        __syncthreads();
    }
    if (i < NN) g_off[i] = sh[t] - v;
    if (t == 1023) g_bsums[blockIdx.x] = sh[1023];
}

__global__ void scan2_kernel(int nb) {
    __shared__ int sh[128];
    int t = threadIdx.x;
    int v = (t < nb) ? g_bsums[t] : 0;
    sh[t] = v;
    __syncthreads();
#pragma unroll
    for (int s = 1; s < 128; s <<= 1) {
        int x = (t >= s) ? sh[t - s] : 0;
        __syncthreads();
        sh[t] += x;
        __syncthreads();
    }
    if (t < nb) g_bsums[t] = sh[t] - v;
}

__global__ void scan3_kernel() {
    int i = blockIdx.x * 1024 + threadIdx.x;
    if (i < NN) {
        int o = g_off[i] + g_bsums[blockIdx.x];
        g_off[i] = o;
        g_cursor[i] = o;
    }
}

__global__ void fill_kernel() {
    long long i = (long long)blockIdx.x * blockDim.x + threadIdx.x;
    if (i < EE) {
        int t = g_tgt[i];
        int p = atomicAdd(&g_cursor[t], 1);
        g_col[p] = g_src[i];
    }
}

// -------- shared GEMM helpers ----------------------------------------------
#define SASTRIDE 40

__device__ __forceinline__ unsigned smaddr(const void* p) {
    return (unsigned)__cvta_generic_to_shared(p);
}

#define LDMX4(R, addr)                                                           \
    asm volatile("ldmatrix.sync.aligned.m8n8.x4.shared.b16 {%0,%1,%2,%3}, [%4];" \
                 : "=r"((R)[0]), "=r"((R)[1]), "=r"((R)[2]), "=r"((R)[3])        \
                 : "r"(addr))

#define MMA16816(C, A, b0, b1)                                                   \
    asm volatile(                                                                \
        "mma.sync.aligned.m16n8k16.row.col.f32.f16.f16.f32 "                     \
        "{%0,%1,%2,%3}, {%4,%5,%6,%7}, {%8,%9}, {%0,%1,%2,%3};"                  \
        : "+f"((C)[0]), "+f"((C)[1]), "+f"((C)[2]), "+f"((C)[3])                 \
        : "r"((A)[0]), "r"((A)[1]), "r"((A)[2]), "r"((A)[3]), "r"(b0), "r"(b1))

// -------- embed GEMM: h = x @ W_embed + b (3-term split, writes hh/hl) ------
// grid (gx, 2): y selects 64-col half. Reads f32 x, splits on the fly.
__global__ void __launch_bounds__(256, 2) gemm_embed(const float* __restrict__ xin,
                                                     const float* __restrict__ bias,
                                                     int nrows) {
    __shared__ __align__(16) __half sAh[128 * SASTRIDE];
    __shared__ __align__(16) __half sAl[128 * SASTRIDE];
    __shared__ __align__(16) __half sWh[64 * SASTRIDE];
    __shared__ __align__(16) __half sWl[64 * SASTRIDE];

    const int colBase = blockIdx.y * 64;
    const __half* Wt_h = g_Wth + (size_t)colBase * HH;
    const __half* Wt_l = g_Wtl + (size_t)colBase * HH;

    const int tid = threadIdx.x;
    const int wid = tid >> 5, lane = tid & 31;
    const int wm = wid >> 1, wn = wid & 1;
    const int rowBase = blockIdx.x * 128;

    float acc[2][4][4];
#pragma unroll
    for (int f = 0; f < 2; f++)
#pragma unroll
        for (int nf = 0; nf < 4; nf++)
#pragma unroll
            for (int q = 0; q < 4; q++) acc[f][nf][q] = 0.0f;

    const int a_r = (lane & 7) + ((lane >> 3) & 1) * 8;
    const int a_k8 = ((lane >> 4) & 1) * 8;
    const int b_n = (lane & 7) + ((lane >> 4) & 1) * 8;
    const int b_k8 = ((lane >> 3) & 1) * 8;

    for (int kc = 0; kc < 4; kc++) {
        const int k0 = kc * 32;
#pragma unroll
        for (int t = 0; t < 2; t++) {
            int idx = tid + t * 256;
            int r = idx >> 2;
            int kq = (idx & 3) * 8;
            int gr = rowBase + r;
            uint4 vh = make_uint4(0, 0, 0, 0), vl = vh;
            if (gr < nrows) {
                const float* xp = xin + (size_t)gr * HH + k0 + kq;
                float4 xa = *(const float4*)xp;
                float4 xb = *(const float4*)(xp + 4);
                __half h0 = __float2half_rn(xa.x), h1 = __float2half_rn(xa.y);
                __half h2 = __float2half_rn(xa.z), h3 = __float2half_rn(xa.w);
                __half h4 = __float2half_rn(xb.x), h5 = __float2half_rn(xb.y);
                __half h6 = __float2half_rn(xb.z), h7 = __float2half_rn(xb.w);
                __half2 p0 = __halves2half2(h0, h1), p1 = __halves2half2(h2, h3);
                __half2 p2 = __halves2half2(h4, h5), p3 = __halves2half2(h6, h7);
                vh = make_uint4(*(unsigned*)&p0, *(unsigned*)&p1,
                                *(unsigned*)&p2, *(unsigned*)&p3);
                __half2 q0 = __halves2half2(__float2half_rn(xa.x - __half2float(h0)),
                                            __float2half_rn(xa.y - __half2float(h1)));
                __half2 q1 = __halves2half2(__float2half_rn(xa.z - __half2float(h2)),
                                            __float2half_rn(xa.w - __half2float(h3)));
                __half2 q2 = __halves2half2(__float2half_rn(xb.x - __half2float(h4)),
                                            __float2half_rn(xb.y - __half2float(h5)));
                __half2 q3 = __halves2half2(__float2half_rn(xb.z - __half2float(h6)),
                                            __float2half_rn(xb.w - __half2float(h7)));
                vl = make_uint4(*(unsigned*)&q0, *(unsigned*)&q1,
                                *(unsigned*)&q2, *(unsigned*)&q3);
            }
            *(uint4*)&sAh[r * SASTRIDE + kq] = vh;
            *(uint4*)&sAl[r * SASTRIDE + kq] = vl;
        }
        {
            int r = tid >> 2;
            int kq = (tid & 3) * 8;
            *(uint4*)&sWh[r * SASTRIDE + kq] = *(const uint4*)(Wt_h + (size_t)r * HH + k0 + kq);
            *(uint4*)&sWl[r * SASTRIDE + kq] = *(const uint4*)(Wt_l + (size_t)r * HH + k0 + kq);
        }
        __syncthreads();

#pragma unroll
        for (int ks = 0; ks < 2; ks++) {
            const int kk = ks * 16;
            unsigned ah[2][4], al[2][4];
#pragma unroll
            for (int f = 0; f < 2; f++) {
                int row = wm * 32 + f * 16 + a_r;
                LDMX4(ah[f], smaddr(&sAh[row * SASTRIDE + kk + a_k8]));
                LDMX4(al[f], smaddr(&sAl[row * SASTRIDE + kk + a_k8]));
            }
            unsigned bh[2][4], bl[2][4];
#pragma unroll
            for (int nb = 0; nb < 2; nb++) {
                int n = wn * 32 + nb * 16 + b_n;
                LDMX4(bh[nb], smaddr(&sWh[n * SASTRIDE + kk + b_k8]));
                LDMX4(bl[nb], smaddr(&sWl[n * SASTRIDE + kk + b_k8]));
            }
#pragma unroll
            for (int f = 0; f < 2; f++) {
#pragma unroll
                for (int nb = 0; nb < 2; nb++) {
                    MMA16816(acc[f][nb * 2],     ah[f], bh[nb][0], bh[nb][1]);
                    MMA16816(acc[f][nb * 2 + 1], ah[f], bh[nb][2], bh[nb][3]);
                    MMA16816(acc[f][nb * 2],     ah[f], bl[nb][0], bl[nb][1]);
                    MMA16816(acc[f][nb * 2 + 1], ah[f], bl[nb][2], bl[nb][3]);
                    MMA16816(acc[f][nb * 2],     al[f], bh[nb][0], bh[nb][1]);
                    MMA16816(acc[f][nb * 2 + 1], al[f], bh[nb][2], bh[nb][3]);
                }
            }
        }
        __syncthreads();
    }

    const int gid = lane >> 2, qid = lane & 3;
#pragma unroll
    for (int f = 0; f < 2; f++) {
        int rbase = rowBase + wm * 32 + f * 16 + gid;
#pragma unroll
        for (int nf = 0; nf < 4; nf++) {
            int col = colBase + wn * 32 + nf * 8 + qid * 2;
#pragma unroll
            for (int half_ = 0; half_ < 2; half_++) {
                int row = rbase + half_ * 8;
                if (row >= nrows) continue;
                float v0 = acc[f][nf][half_ * 2] + bias[col];
                float v1 = acc[f][nf][half_ * 2 + 1] + bias[col + 1];
                size_t o = (size_t)row * HH + col;
                __half h0 = __float2half_rn(v0), h1 = __float2half_rn(v1);
                *(__half2*)(g_hh + o) = __halves2half2(h0, h1);
                *(__half2*)(g_hl + o) =
                    __halves2half2(__float2half_rn(v0 - __half2float(h0)),
                                   __float2half_rn(v1 - __half2float(h1)));
            }
        }
    }
}

// -------- layer GEMM: A/B = hh @ (Wh+Wl), double-buffered, 2-term split -----
// grid (gx, 4): y>>1 selects matrix (A/B), y&1 selects 64-col half.
// Reads g_hh only (hl correction term dropped: ~2^-11.5 rel, absorbed by pool).
__global__ void __launch_bounds__(256, 2) gemm_layer(int mat0, int nrows) {
    __shared__ __align__(16) __half sA[2][128 * SASTRIDE];
    __shared__ __align__(16) __half sWh[2][64 * SASTRIDE];
    __shared__ __align__(16) __half sWl[2][64 * SASTRIDE];

    const int matSel = blockIdx.y >> 1;
    const int colBase = (blockIdx.y & 1) * 64;
    const int mat = mat0 + matSel;
    const __half* Wt_h = g_Wth + (size_t)mat * HH * HH + (size_t)colBase * HH;
    const __half* Wt_l = g_Wtl + (size_t)mat * HH * HH + (size_t)colBase * HH;

    const int tid = threadIdx.x;
    const int wid = tid >> 5, lane = tid & 31;
    const int wm = wid >> 1, wn = wid & 1;   // warp tile 32x32
    const int rowBase = blockIdx.x * 128;

    const int s_r = tid >> 2;            // 0..63
    const int s_kq = (tid & 3) * 8;
    const int gr0 = rowBase + s_r;
    const int gr1 = gr0 + 64;

    float acc[2][4][4];
#pragma unroll
    for (int f = 0; f < 2; f++)
#pragma unroll
        for (int nf = 0; nf < 4; nf++)
#pragma unroll
            for (int q = 0; q < 4; q++) acc[f][nf][q] = 0.0f;

    const int a_r = (lane & 7) + ((lane >> 3) & 1) * 8;
    const int a_k8 = ((lane >> 4) & 1) * 8;
    const int b_n = (lane & 7) + ((lane >> 4) & 1) * 8;
    const int b_k8 = ((lane >> 3) & 1) * 8;

    uint4 ra0, ra1, rwh, rwl;

#define LOAD_STAGE(kc)                                                                     \
    do {                                                                                   \
        int k0_ = (kc) * 32;                                                               \
        ra0 = (gr0 < nrows) ? *(const uint4*)(g_hh + (size_t)gr0 * HH + k0_ + s_kq)        \
                            : make_uint4(0, 0, 0, 0);                                      \
        ra1 = (gr1 < nrows) ? *(const uint4*)(g_hh + (size_t)gr1 * HH + k0_ + s_kq)        \
                            : make_uint4(0, 0, 0, 0);                                      \
        rwh = *(const uint4*)(Wt_h + (size_t)s_r * HH + k0_ + s_kq);                       \
        rwl = *(const uint4*)(Wt_l + (size_t)s_r * HH + k0_ + s_kq);                       \
    } while (0)

#define STORE_STAGE(s)                                                                     \
    do {                                                                                   \
        *(uint4*)&sA[s][s_r * SASTRIDE + s_kq] = ra0;                                      \
        *(uint4*)&sA[s][(s_r + 64) * SASTRIDE + s_kq] = ra1;                               \
        *(uint4*)&sWh[s][s_r * SASTRIDE + s_kq] = rwh;                                     \
        *(uint4*)&sWl[s][s_r * SASTRIDE + s_kq] = rwl;                                     \
    } while (0)

    LOAD_STAGE(0);
    STORE_STAGE(0);
    __syncthreads();

#pragma unroll
    for (int kc = 0; kc < 4; kc++) {
        if (kc < 3) LOAD_STAGE(kc + 1);
        const int s = kc & 1;
#pragma unroll
        for (int ks = 0; ks < 2; ks++) {
            const int kk = ks * 16;
            unsigned ah[2][4];
#pragma unroll
            for (int f = 0; f < 2; f++) {
                int row = wm * 32 + f * 16 + a_r;
                LDMX4(ah[f], smaddr(&sA[s][row * SASTRIDE + kk + a_k8]));
            }
            unsigned bh[2][4], bl[2][4];
#pragma unroll
            for (int nb = 0; nb < 2; nb++) {
                int n = wn * 32 + nb * 16 + b_n;
                LDMX4(bh[nb], smaddr(&sWh[s][n * SASTRIDE + kk + b_k8]));
                LDMX4(bl[nb], smaddr(&sWl[s][n * SASTRIDE + kk + b_k8]));
            }
#pragma unroll
            for (int f = 0; f < 2; f++) {
#pragma unroll
                for (int nb = 0; nb < 2; nb++) {
                    MMA16816(acc[f][nb * 2],     ah[f], bh[nb][0], bh[nb][1]);
                    MMA16816(acc[f][nb * 2 + 1], ah[f], bh[nb][2], bh[nb][3]);
                    MMA16816(acc[f][nb * 2],     ah[f], bl[nb][0], bl[nb][1]);
                    MMA16816(acc[f][nb * 2 + 1], ah[f], bl[nb][2], bl[nb][3]);
                }
            }
        }
        if (kc < 3) {
            STORE_STAGE((kc + 1) & 1);
            __syncthreads();
        }
    }
#undef LOAD_STAGE
#undef STORE_STAGE

    const int gid = lane >> 2, qid = lane & 3;
    __half* outh = matSel ? g_Bh : g_Ah;
#pragma unroll
    for (int f = 0; f < 2; f++) {
        int rbase = rowBase + wm * 32 + f * 16 + gid;
#pragma unroll
        for (int nf = 0; nf < 4; nf++) {
            int col = colBase + wn * 32 + nf * 8 + qid * 2;
#pragma unroll
            for (int half_ = 0; half_ < 2; half_++) {
                int row = rbase + half_ * 8;
                if (row >= nrows) continue;
                *(__half2*)(outh + (size_t)row * HH + col) =
                    __floats2half2_rn(acc[f][nf][half_ * 2], acc[f][nf][half_ * 2 + 1]);
            }
        }
    }
}

// -------- fused aggregate + residual + relu + split (atomic-free via CSR) --
__global__ void __launch_bounds__(128) gather_relu(const float* __restrict__ bm, int nrows) {
    int t = blockIdx.x * 4 + threadIdx.y;
    if (t >= nrows) return;
    int lane = threadIdx.x;
    int d = g_deg[t];
    int o = g_off[t];
    size_t base = (size_t)t * HH + lane * 4;

    float4 bmv = *(const float4*)(bm + lane * 4);
    uint2 bvp = *(const uint2*)(g_Bh + base);
    float2 bq0 = __half22float2(*(__half2*)&bvp.x);
    float2 bq1 = __half22float2(*(__half2*)&bvp.y);
    float dd = (float)d;
    float4 acc;
    acc.x = dd * (bq0.x + bmv.x);
    acc.y = dd * (bq0.y + bmv.y);
    acc.z = dd * (bq1.x + bmv.z);
    acc.w = dd * (bq1.y + bmv.w);

    int i = 0;
    for (; i + 4 <= d; i += 4) {
        int s0 = g_col[o + i];
        int s1 = g_col[o + i + 1];
        int s2 = g_col[o + i + 2];
        int s3 = g_col[o + i + 3];
        uint2 v0 = *(const uint2*)(g_Ah + (size_t)s0 * HH + lane * 4);
        uint2 v1 = *(const uint2*)(g_Ah + (size_t)s1 * HH + lane * 4);
        uint2 v2 = *(const uint2*)(g_Ah + (size_t)s2 * HH + lane * 4);
        uint2 v3 = *(const uint2*)(g_Ah + (size_t)s3 * HH + lane * 4);
        float2 a0 = __half22float2(*(__half2*)&v0.x), a1 = __half22float2(*(__half2*)&v0.y);
        float2 b0 = __half22float2(*(__half2*)&v1.x), b1 = __half22float2(*(__half2*)&v1.y);
        float2 c0 = __half22float2(*(__half2*)&v2.x), c1 = __half22float2(*(__half2*)&v2.y);
        float2 d0 = __half22float2(*(__half2*)&v3.x), d1 = __half22float2(*(__half2*)&v3.y);
        acc.x += (a0.x + b0.x) + (c0.x + d0.x);
        acc.y += (a0.y + b0.y) + (c0.y + d0.y);
        acc.z += (a1.x + b1.x) + (c1.x + d1.x);
        acc.w += (a1.y + b1.y) + (c1.y + d1.y);
    }
    for (; i < d; i++) {
        int s0 = g_col[o + i];
        uint2 v0 = *(const uint2*)(g_Ah + (size_t)s0 * HH + lane * 4);
        float2 a0 = __half22float2(*(__half2*)&v0.x);
        float2 a1 = __half22float2(*(__half2*)&v0.y);
        acc.x += a0.x;
        acc.y += a0.y;
        acc.z += a1.x;
        acc.w += a1.y;
    }

    // residual from split representation (hh + hl)
    uint2 hh2 = *(const uint2*)(g_hh + base);
    uint2 hl2 = *(const uint2*)(g_hl + base);
    float2 h0 = __half22float2(*(__half2*)&hh2.x);
    float2 h1 = __half22float2(*(__half2*)&hh2.y);
    float2 l0 = __half22float2(*(__half2*)&hl2.x);
    float2 l1 = __half22float2(*(__half2*)&hl2.y);
    float4 v;
    v.x = fmaxf(h0.x + l0.x + acc.x, 0.0f);
    v.y = fmaxf(h0.y + l0.y + acc.y, 0.0f);
    v.z = fmaxf(h1.x + l1.x + acc.z, 0.0f);
    v.w = fmaxf(h1.y + l1.y + acc.w, 0.0f);

    __half a0 = __float2half_rn(v.x), a1 = __float2half_rn(v.y);
    __half a2 = __float2half_rn(v.z), a3 = __float2half_rn(v.w);
    __half2 hi0 = __halves2half2(a0, a1), hi1 = __halves2half2(a2, a3);
    __half2 lo0 = __halves2half2(__float2half_rn(v.x - __half2float(a0)),
                                 __float2half_rn(v.y - __half2float(a1)));
    __half2 lo1 = __halves2half2(__float2half_rn(v.z - __half2float(a2)),
                                 __float2half_rn(v.w - __half2float(a3)));
    uint2 ph, pl;
    ph.x = *(unsigned*)&hi0; ph.y = *(unsigned*)&hi1;
    pl.x = *(unsigned*)&lo0; pl.y = *(unsigned*)&lo1;
    *(uint2*)(g_hh + base) = ph;
    *(uint2*)(g_hl + base) = pl;
}

// -------- per-graph mean pool (h = hh + hl) --------
__global__ void __launch_bounds__(128) pool_kernel() {
    int c = threadIdx.x;
    int n0 = blockIdx.x * 512;
    if (n0 >= NN) return;
    int n1 = n0 + 512;
    if (n1 > NN) n1 = NN;
    int curb = g_batchi[n0];
    float acc = 0.0f;
    for (int n = n0; n < n1; n++) {
        int b = g_batchi[n];
        if (b != curb) {
            atomicAdd(&g_gsum[curb * HH + c], acc);
            acc = 0.0f;
            curb = b;
        }
        size_t idx = (size_t)n * HH + c;
        acc += __half2float(g_hh[idx]) + __half2float(g_hl[idx]);
    }
    atomicAdd(&g_gsum[curb * HH + c], acc);
}

// -------- readout --------
__global__ void r1_kernel(const float* __restrict__ W1, const float* __restrict__ b1) {
    int idx = blockIdx.x * blockDim.x + threadIdx.x;
    if (idx >= BB * 2 * HH) return;
    int b = idx >> 8;
    int j = idx & 255;
    int cnt = g_cnt[b];
    float inv = 1.0f / (float)(cnt > 0 ? cnt : 1);
    float s = 0.0f;
#pragma unroll 8
    for (int k = 0; k < HH; k++) s = fmaf(g_gsum[b * HH + k], W1[(size_t)k * 256 + j], s);
    s = s * inv + b1[j];
    g_t1[idx] = s > 0.0f ? s : 0.0f;
}

__global__ void r2_kernel(const float* __restrict__ W2, const float* __restrict__ b2,
                          float* __restrict__ out) {
    int idx = blockIdx.x * blockDim.x + threadIdx.x;
    if (idx >= BB * MM) return;
    int b = idx >> 11;
    int m = idx & 2047;
    float s = b2[m];
#pragma unroll 8
    for (int k = 0; k < 2 * HH; k++)
        s = fmaf(g_t1[b * 2 * HH + k], W2[(size_t)k * MM + m], s);
    float sig = 1.0f / (1.0f + expf(-s));
    out[idx] = sig * 6.283185307179586f;
}

// ----------------------------------------------------------------
extern "C" void kernel_launch(void* const* d_in, const int* in_sizes, int n_in,
                              void* d_out, int out_size) {
    const float* x       = (const float*)d_in[0];
    const void*  eidx    = d_in[1];
    const void*  batchp  = d_in[2];
    const float* W_embed = (const float*)d_in[3];
    const float* b_embed = (const float*)d_in[4];
    const float* Wm      = (const float*)d_in[5];
    const float* bm      = (const float*)d_in[6];
    const float* W1      = (const float*)d_in[7];
    const float* b1      = (const float*)d_in[8];
    const float* W2      = (const float*)d_in[9];
    const float* b2      = (const float*)d_in[10];
    float* out = (float*)d_out;

    int nrows = in_sizes[0] / HH;
    if (nrows > NN) nrows = NN;

    const int nb_scan = (NN + 1023) / 1024;
    const int eg = (EE + 255) / 256;
    const int gx = (nrows + 127) / 128;

    zero_kernel<<<(NN + 255) / 256, 256>>>();
    detect_kernel<<<1, 256>>>(eidx, batchp);
    prep_kernel<<<(7 * HH * HH + 255) / 256, 256>>>(W_embed, Wm);
    gemm_embed<<<dim3(gx, 2), 256>>>(x, b_embed, nrows);   // launch #4 (ncu)

    convert_kernel<<<eg, 256>>>(eidx, batchp);
    scan1_kernel<<<nb_scan, 1024>>>();
    scan2_kernel<<<1, 128>>>(nb_scan);
    scan3_kernel<<<nb_scan, 1024>>>();
    fill_kernel<<<eg, 256>>>();

    for (int l = 0; l < LL; l++) {
        gemm_layer<<<dim3(gx, 4), 256>>>(1 + 2 * l, nrows);
        gather_relu<<<(nrows + 3) / 4, dim3(32, 4)>>>(bm + (size_t)l * HH, nrows);
    }

    pool_kernel<<<(NN + 511) / 512, 128>>>();
    r1_kernel<<<(BB * 2 * HH + 255) / 256, 256>>>(W1, b1);
    r2_kernel<<<(BB * MM + 255) / 256, 256>>>(W2, b2, out);
}

// round 8
// speedup vs baseline: 1.9956x; 1.1175x over previous
#include <cuda_runtime.h>
#include <cuda_fp16.h>
#include <math.h>

// Problem constants (fixed shapes)
#define NN 100000
#define EE 1600000
#define HH 128
#define BB 16
#define MM 2048
#define LL 3

// -------- static device scratch (no allocations allowed) --------
__device__ __half g_Ah[(size_t)NN * HH];   // h @ Wm_top (fp16)
__device__ __half g_Bh[(size_t)NN * HH];   // h @ Wm_bot (fp16)
__device__ __half g_hh[(size_t)NN * HH];   // node hidden state (fp16)
__device__ __half g_Wth[7 * HH * HH];      // W^T hi splits
__device__ __half g_Wtl[7 * HH * HH];      // W^T lo splits
__device__ int    g_src[EE];
__device__ int    g_tgt[EE];
__device__ int    g_col[EE];
__device__ int    g_deg[NN];
__device__ int    g_off[NN];
__device__ int    g_cursor[NN];
__device__ int    g_batchi[NN];
__device__ int    g_bsums[128];
__device__ float  g_gsum[BB * HH];
__device__ int    g_cnt[BB];
__device__ float  g_t1[BB * 2 * HH];
__device__ int    g_flags;

// ----------------------------------------------------------------
__global__ void zero_kernel() {
    int i = blockIdx.x * blockDim.x + threadIdx.x;
    if (i < NN) g_deg[i] = 0;
    if (i < BB * HH) g_gsum[i] = 0.0f;
    if (i < BB) g_cnt[i] = 0;
    if (i == 0) g_flags = 0;
}

__global__ void detect_kernel(const void* __restrict__ ep, const void* __restrict__ bp) {
    int j = threadIdx.x;
    long long pos = (long long)j * (EE / 256);
    long long v = ((const long long*)ep)[pos];
    if (v < 0 || v >= NN) atomicOr(&g_flags, 1);
    long long bpos = (long long)(NN / 4) + j;
    long long bv = ((const long long*)bp)[bpos];
    if (bv < 0 || bv >= BB) atomicOr(&g_flags, 2);
}

// weight transpose + fp16 hi/lo split
__global__ void prep_kernel(const float* __restrict__ We, const float* __restrict__ Wm) {
    int idx = blockIdx.x * blockDim.x + threadIdx.x;
    if (idx >= 7 * HH * HH) return;
    int mat = idx >> 14;
    int r = (idx >> 7) & 127;  // k
    int c = idx & 127;         // n
    float v;
    if (mat == 0) {
        v = We[r * HH + c];
    } else {
        int l = (mat - 1) >> 1;
        int hf = (mat - 1) & 1;
        v = Wm[((size_t)l * 2 * HH + hf * HH + r) * HH + c];
    }
    __half hi = __float2half_rn(v);
    g_Wth[mat * HH * HH + c * HH + r] = hi;
    g_Wtl[mat * HH * HH + c * HH + r] = __float2half_rn(v - __half2float(hi));
}

__global__ void convert_kernel(const void* __restrict__ ep, const void* __restrict__ bp) {
    int f = g_flags;
    long long i = (long long)blockIdx.x * blockDim.x + threadIdx.x;
    if (i < EE) {
        long long s, t;
        if (f & 1) {
            s = ((const int*)ep)[i];
            t = ((const int*)ep)[EE + i];
        } else {
            s = ((const long long*)ep)[i];
            t = ((const long long*)ep)[EE + i];
        }
        g_src[i] = (int)s;
        g_tgt[i] = (int)t;
        atomicAdd(&g_deg[(int)t], 1);
    }
    if (i < NN) {
        int b = (f & 2) ? ((const int*)bp)[i] : (int)((const long long*)bp)[i];
        g_batchi[i] = b;
        atomicAdd(&g_cnt[b], 1);
    }
}

__global__ void scan1_kernel() {
    __shared__ int sh[1024];
    int t = threadIdx.x;
    int i = blockIdx.x * 1024 + t;
    int v = (i < NN) ? g_deg[i] : 0;
    sh[t] = v;
    __syncthreads();
#pragma unroll
    for (int s = 1; s < 1024; s <<= 1) {
        int x = (t >= s) ? sh[t - s] : 0;
        __syncthreads();
        sh[t] += x;
        __syncthreads();
    }
    if (i < NN) g_off[i] = sh[t] - v;
    if (t == 1023) g_bsums[blockIdx.x] = sh[1023];
}

__global__ void scan2_kernel(int nb) {
    __shared__ int sh[128];
    int t = threadIdx.x;
    int v = (t < nb) ? g_bsums[t] : 0;
    sh[t] = v;
    __syncthreads();
#pragma unroll
    for (int s = 1; s < 128; s <<= 1) {
        int x = (t >= s) ? sh[t - s] : 0;
        __syncthreads();
        sh[t] += x;
        __syncthreads();
    }
    if (t < nb) g_bsums[t] = sh[t] - v;
}

__global__ void scan3_kernel() {
    int i = blockIdx.x * 1024 + threadIdx.x;
    if (i < NN) {
        int o = g_off[i] + g_bsums[blockIdx.x];
        g_off[i] = o;
        g_cursor[i] = o;
    }
}

__global__ void fill_kernel() {
    long long i = (long long)blockIdx.x * blockDim.x + threadIdx.x;
    if (i < EE) {
        int t = g_tgt[i];
        int p = atomicAdd(&g_cursor[t], 1);
        g_col[p] = g_src[i];
    }
}

// -------- shared GEMM helpers ----------------------------------------------
#define SASTRIDE 40

__device__ __forceinline__ unsigned smaddr(const void* p) {
    return (unsigned)__cvta_generic_to_shared(p);
}

#define LDMX4(R, addr)                                                           \
    asm volatile("ldmatrix.sync.aligned.m8n8.x4.shared.b16 {%0,%1,%2,%3}, [%4];" \
                 : "=r"((R)[0]), "=r"((R)[1]), "=r"((R)[2]), "=r"((R)[3])        \
                 : "r"(addr))

#define MMA16816(C, A, b0, b1)                                                   \
    asm volatile(                                                                \
        "mma.sync.aligned.m16n8k16.row.col.f32.f16.f16.f32 "                     \
        "{%0,%1,%2,%3}, {%4,%5,%6,%7}, {%8,%9}, {%0,%1,%2,%3};"                  \
        : "+f"((C)[0]), "+f"((C)[1]), "+f"((C)[2]), "+f"((C)[3])                 \
        : "r"((A)[0]), "r"((A)[1]), "r"((A)[2]), "r"((A)[3]), "r"(b0), "r"(b1))

// Core double-buffered 2-term mainloop shared by embed/layer kernels.
// sA: 128 rows staged fp16; W hi+lo 64 rows. acc covers warp tile 32x32.
#define GEMM_MAINLOOP(LOAD_STAGE, STORE_STAGE)                                    \
    LOAD_STAGE(0);                                                                \
    STORE_STAGE(0);                                                               \
    __syncthreads();                                                              \
    _Pragma("unroll") for (int kc = 0; kc < 4; kc++) {                            \
        if (kc < 3) LOAD_STAGE(kc + 1);                                           \
        const int s = kc & 1;                                                     \
        _Pragma("unroll") for (int ks = 0; ks < 2; ks++) {                        \
            const int kk = ks * 16;                                               \
            unsigned ah[2][4];                                                    \
            _Pragma("unroll") for (int f = 0; f < 2; f++) {                       \
                int row = wm * 32 + f * 16 + a_r;                                 \
                LDMX4(ah[f], smaddr(&sA[s][row * SASTRIDE + kk + a_k8]));         \
            }                                                                     \
            unsigned bh[2][4], bl[2][4];                                          \
            _Pragma("unroll") for (int nb = 0; nb < 2; nb++) {                    \
                int n = wn * 32 + nb * 16 + b_n;                                  \
                LDMX4(bh[nb], smaddr(&sWh[s][n * SASTRIDE + kk + b_k8]));         \
                LDMX4(bl[nb], smaddr(&sWl[s][n * SASTRIDE + kk + b_k8]));         \
            }                                                                     \
            _Pragma("unroll") for (int f = 0; f < 2; f++) {                       \
                _Pragma("unroll") for (int nb = 0; nb < 2; nb++) {                \
                    MMA16816(acc[f][nb * 2],     ah[f], bh[nb][0], bh[nb][1]);    \
                    MMA16816(acc[f][nb * 2 + 1], ah[f], bh[nb][2], bh[nb][3]);    \
                    MMA16816(acc[f][nb * 2],     ah[f], bl[nb][0], bl[nb][1]);    \
                    MMA16816(acc[f][nb * 2 + 1], ah[f], bl[nb][2], bl[nb][3]);    \
                }                                                                 \
            }                                                                     \
        }                                                                         \
        if (kc < 3) {                                                             \
            STORE_STAGE((kc + 1) & 1);                                            \
            __syncthreads();                                                      \
        }                                                                         \
    }

// -------- embed GEMM: h = fp16(x) @ W_embed + b, double-buffered ------------
// grid (gx, 2): y selects 64-col half. Writes g_hh (fp16).
__global__ void __launch_bounds__(256, 2) gemm_embed(const float* __restrict__ xin,
                                                     const float* __restrict__ bias,
                                                     int nrows) {
    __shared__ __align__(16) __half sA[2][128 * SASTRIDE];
    __shared__ __align__(16) __half sWh[2][64 * SASTRIDE];
    __shared__ __align__(16) __half sWl[2][64 * SASTRIDE];

    const int colBase = blockIdx.y * 64;
    const __half* Wt_h = g_Wth + (size_t)colBase * HH;
    const __half* Wt_l = g_Wtl + (size_t)colBase * HH;

    const int tid = threadIdx.x;
    const int wid = tid >> 5, lane = tid & 31;
    const int wm = wid >> 1, wn = wid & 1;
    const int rowBase = blockIdx.x * 128;

    const int s_r = tid >> 2;
    const int s_kq = (tid & 3) * 8;
    const int gr0 = rowBase + s_r;
    const int gr1 = gr0 + 64;

    float acc[2][4][4];
#pragma unroll
    for (int f = 0; f < 2; f++)
#pragma unroll
        for (int nf = 0; nf < 4; nf++)
#pragma unroll
            for (int q = 0; q < 4; q++) acc[f][nf][q] = 0.0f;

    const int a_r = (lane & 7) + ((lane >> 3) & 1) * 8;
    const int a_k8 = ((lane >> 4) & 1) * 8;
    const int b_n = (lane & 7) + ((lane >> 4) & 1) * 8;
    const int b_k8 = ((lane >> 3) & 1) * 8;

    uint4 ra0, ra1, rwh, rwl;

#define CVT8(dst, gp)                                                             \
    do {                                                                          \
        float4 xa = *(const float4*)(gp);                                        \
        float4 xb = *(const float4*)((gp) + 4);                                  \
        __half2 p0 = __floats2half2_rn(xa.x, xa.y);                              \
        __half2 p1 = __floats2half2_rn(xa.z, xa.w);                              \
        __half2 p2 = __floats2half2_rn(xb.x, xb.y);                              \
        __half2 p3 = __floats2half2_rn(xb.z, xb.w);                              \
        dst = make_uint4(*(unsigned*)&p0, *(unsigned*)&p1,                        \
                         *(unsigned*)&p2, *(unsigned*)&p3);                       \
    } while (0)

#define E_LOAD_STAGE(kc)                                                          \
    do {                                                                          \
        int k0_ = (kc) * 32;                                                      \
        if (gr0 < nrows) CVT8(ra0, xin + (size_t)gr0 * HH + k0_ + s_kq);          \
        else ra0 = make_uint4(0, 0, 0, 0);                                        \
        if (gr1 < nrows) CVT8(ra1, xin + (size_t)gr1 * HH + k0_ + s_kq);          \
        else ra1 = make_uint4(0, 0, 0, 0);                                        \
        rwh = *(const uint4*)(Wt_h + (size_t)s_r * HH + k0_ + s_kq);              \
        rwl = *(const uint4*)(Wt_l + (size_t)s_r * HH + k0_ + s_kq);              \
    } while (0)

#define E_STORE_STAGE(s)                                                          \
    do {                                                                          \
        *(uint4*)&sA[s][s_r * SASTRIDE + s_kq] = ra0;                             \
        *(uint4*)&sA[s][(s_r + 64) * SASTRIDE + s_kq] = ra1;                      \
        *(uint4*)&sWh[s][s_r * SASTRIDE + s_kq] = rwh;                            \
        *(uint4*)&sWl[s][s_r * SASTRIDE + s_kq] = rwl;                            \
    } while (0)

    GEMM_MAINLOOP(E_LOAD_STAGE, E_STORE_STAGE)
#undef E_LOAD_STAGE
#undef E_STORE_STAGE
#undef CVT8

    const int gid = lane >> 2, qid = lane & 3;
#pragma unroll
    for (int f = 0; f < 2; f++) {
        int rbase = rowBase + wm * 32 + f * 16 + gid;
#pragma unroll
        for (int nf = 0; nf < 4; nf++) {
            int col = colBase + wn * 32 + nf * 8 + qid * 2;
            float bx = bias[col], by = bias[col + 1];
#pragma unroll
            for (int half_ = 0; half_ < 2; half_++) {
                int row = rbase + half_ * 8;
                if (row >= nrows) continue;
                *(__half2*)(g_hh + (size_t)row * HH + col) =
                    __floats2half2_rn(acc[f][nf][half_ * 2] + bx,
                                      acc[f][nf][half_ * 2 + 1] + by);
            }
        }
    }
}

// -------- layer GEMM: A/B = hh @ (Wh+Wl), double-buffered, 2-term -----------
// grid (gx, 4): y>>1 selects matrix (A/B), y&1 selects 64-col half.
__global__ void __launch_bounds__(256, 2) gemm_layer(int mat0, int nrows) {
    __shared__ __align__(16) __half sA[2][128 * SASTRIDE];
    __shared__ __align__(16) __half sWh[2][64 * SASTRIDE];
    __shared__ __align__(16) __half sWl[2][64 * SASTRIDE];

    const int matSel = blockIdx.y >> 1;
    const int colBase = (blockIdx.y & 1) * 64;
    const int mat = mat0 + matSel;
    const __half* Wt_h = g_Wth + (size_t)mat * HH * HH + (size_t)colBase * HH;
    const __half* Wt_l = g_Wtl + (size_t)mat * HH * HH + (size_t)colBase * HH;

    const int tid = threadIdx.x;
    const int wid = tid >> 5, lane = tid & 31;
    const int wm = wid >> 1, wn = wid & 1;
    const int rowBase = blockIdx.x * 128;

    const int s_r = tid >> 2;
    const int s_kq = (tid & 3) * 8;
    const int gr0 = rowBase + s_r;
    const int gr1 = gr0 + 64;

    float acc[2][4][4];
#pragma unroll
    for (int f = 0; f < 2; f++)
#pragma unroll
        for (int nf = 0; nf < 4; nf++)
#pragma unroll
            for (int q = 0; q < 4; q++) acc[f][nf][q] = 0.0f;

    const int a_r = (lane & 7) + ((lane >> 3) & 1) * 8;
    const int a_k8 = ((lane >> 4) & 1) * 8;
    const int b_n = (lane & 7) + ((lane >> 4) & 1) * 8;
    const int b_k8 = ((lane >> 3) & 1) * 8;

    uint4 ra0, ra1, rwh, rwl;

#define L_LOAD_STAGE(kc)                                                                   \
    do {                                                                                   \
        int k0_ = (kc) * 32;                                                               \
        ra0 = (gr0 < nrows) ? *(const uint4*)(g_hh + (size_t)gr0 * HH + k0_ + s_kq)        \
                            : make_uint4(0, 0, 0, 0);                                      \
        ra1 = (gr1 < nrows) ? *(const uint4*)(g_hh + (size_t)gr1 * HH + k0_ + s_kq)        \
                            : make_uint4(0, 0, 0, 0);                                      \
        rwh = *(const uint4*)(Wt_h + (size_t)s_r * HH + k0_ + s_kq);                       \
        rwl = *(const uint4*)(Wt_l + (size_t)s_r * HH + k0_ + s_kq);                       \
    } while (0)

#define L_STORE_STAGE(s)                                                                   \
    do {                                                                                   \
        *(uint4*)&sA[s][s_r * SASTRIDE + s_kq] = ra0;                                      \
        *(uint4*)&sA[s][(s_r + 64) * SASTRIDE + s_kq] = ra1;                               \
        *(uint4*)&sWh[s][s_r * SASTRIDE + s_kq] = rwh;                                     \
        *(uint4*)&sWl[s][s_r * SASTRIDE + s_kq] = rwl;                                     \
    } while (0)

    GEMM_MAINLOOP(L_LOAD_STAGE, L_STORE_STAGE)
#undef L_LOAD_STAGE
#undef L_STORE_STAGE

    const int gid = lane >> 2, qid = lane & 3;
    __half* outh = matSel ? g_Bh : g_Ah;
#pragma unroll
    for (int f = 0; f < 2; f++) {
        int rbase = rowBase + wm * 32 + f * 16 + gid;
#pragma unroll
        for (int nf = 0; nf < 4; nf++) {
            int col = colBase + wn * 32 + nf * 8 + qid * 2;
#pragma unroll
            for (int half_ = 0; half_ < 2; half_++) {
                int row = rbase + half_ * 8;
                if (row >= nrows) continue;
                *(__half2*)(outh + (size_t)row * HH + col) =
                    __floats2half2_rn(acc[f][nf][half_ * 2], acc[f][nf][half_ * 2 + 1]);
            }
        }
    }
}

// -------- fused aggregate + residual + relu (atomic-free via CSR) -----------
__global__ void __launch_bounds__(128) gather_relu(const float* __restrict__ bm, int nrows) {
    int t = blockIdx.x * 4 + threadIdx.y;
    if (t >= nrows) return;
    int lane = threadIdx.x;
    int d = g_deg[t];
    int o = g_off[t];
    size_t base = (size_t)t * HH + lane * 4;

    float4 bmv = *(const float4*)(bm + lane * 4);
    uint2 bvp = *(const uint2*)(g_Bh + base);
    float2 bq0 = __half22float2(*(__half2*)&bvp.x);
    float2 bq1 = __half22float2(*(__half2*)&bvp.y);
    float dd = (float)d;
    float4 acc;
    acc.x = dd * (bq0.x + bmv.x);
    acc.y = dd * (bq0.y + bmv.y);
    acc.z = dd * (bq1.x + bmv.z);
    acc.w = dd * (bq1.y + bmv.w);

    int i = 0;
    for (; i + 4 <= d; i += 4) {
        int s0 = g_col[o + i];
        int s1 = g_col[o + i + 1];
        int s2 = g_col[o + i + 2];
        int s3 = g_col[o + i + 3];
        uint2 v0 = *(const uint2*)(g_Ah + (size_t)s0 * HH + lane * 4);
        uint2 v1 = *(const uint2*)(g_Ah + (size_t)s1 * HH + lane * 4);
        uint2 v2 = *(const uint2*)(g_Ah + (size_t)s2 * HH + lane * 4);
        uint2 v3 = *(const uint2*)(g_Ah + (size_t)s3 * HH + lane * 4);
        float2 a0 = __half22float2(*(__half2*)&v0.x), a1 = __half22float2(*(__half2*)&v0.y);
        float2 b0 = __half22float2(*(__half2*)&v1.x), b1 = __half22float2(*(__half2*)&v1.y);
        float2 c0 = __half22float2(*(__half2*)&v2.x), c1 = __half22float2(*(__half2*)&v2.y);
        float2 d0 = __half22float2(*(__half2*)&v3.x), d1 = __half22float2(*(__half2*)&v3.y);
        acc.x += (a0.x + b0.x) + (c0.x + d0.x);
        acc.y += (a0.y + b0.y) + (c0.y + d0.y);
        acc.z += (a1.x + b1.x) + (c1.x + d1.x);
        acc.w += (a1.y + b1.y) + (c1.y + d1.y);
    }
    for (; i < d; i++) {
        int s0 = g_col[o + i];
        uint2 v0 = *(const uint2*)(g_Ah + (size_t)s0 * HH + lane * 4);
        float2 a0 = __half22float2(*(__half2*)&v0.x);
        float2 a1 = __half22float2(*(__half2*)&v0.y);
        acc.x += a0.x;
        acc.y += a0.y;
        acc.z += a1.x;
        acc.w += a1.y;
    }

    uint2 hh2 = *(const uint2*)(g_hh + base);
    float2 h0 = __half22float2(*(__half2*)&hh2.x);
    float2 h1 = __half22float2(*(__half2*)&hh2.y);
    float4 v;
    v.x = fmaxf(h0.x + acc.x, 0.0f);
    v.y = fmaxf(h0.y + acc.y, 0.0f);
    v.z = fmaxf(h1.x + acc.z, 0.0f);
    v.w = fmaxf(h1.y + acc.w, 0.0f);

    __half2 o0 = __floats2half2_rn(v.x, v.y);
    __half2 o1 = __floats2half2_rn(v.z, v.w);
    uint2 ph;
    ph.x = *(unsigned*)&o0;
    ph.y = *(unsigned*)&o1;
    *(uint2*)(g_hh + base) = ph;
}

// -------- per-graph mean pool --------
__global__ void __launch_bounds__(128) pool_kernel() {
    int c = threadIdx.x;
    int n0 = blockIdx.x * 512;
    if (n0 >= NN) return;
    int n1 = n0 + 512;
    if (n1 > NN) n1 = NN;
    int curb = g_batchi[n0];
    float acc = 0.0f;
    for (int n = n0; n < n1; n++) {
        int b = g_batchi[n];
        if (b != curb) {
            atomicAdd(&g_gsum[curb * HH + c], acc);
            acc = 0.0f;
            curb = b;
        }
        acc += __half2float(g_hh[(size_t)n * HH + c]);
    }
    atomicAdd(&g_gsum[curb * HH + c], acc);
}

// -------- readout --------
__global__ void r1_kernel(const float* __restrict__ W1, const float* __restrict__ b1) {
    int idx = blockIdx.x * blockDim.x + threadIdx.x;
    if (idx >= BB * 2 * HH) return;
    int b = idx >> 8;
    int j = idx & 255;
    int cnt = g_cnt[b];
    float inv = 1.0f / (float)(cnt > 0 ? cnt : 1);
    float s = 0.0f;
#pragma unroll 8
    for (int k = 0; k < HH; k++) s = fmaf(g_gsum[b * HH + k], W1[(size_t)k * 256 + j], s);
    s = s * inv + b1[j];
    g_t1[idx] = s > 0.0f ? s : 0.0f;
}

__global__ void r2_kernel(const float* __restrict__ W2, const float* __restrict__ b2,
                          float* __restrict__ out) {
    int idx = blockIdx.x * blockDim.x + threadIdx.x;
    if (idx >= BB * MM) return;
    int b = idx >> 11;
    int m = idx & 2047;
    float s = b2[m];
#pragma unroll 8
    for (int k = 0; k < 2 * HH; k++)
        s = fmaf(g_t1[b * 2 * HH + k], W2[(size_t)k * MM + m], s);
    float sig = 1.0f / (1.0f + expf(-s));
    out[idx] = sig * 6.283185307179586f;
}

// ----------------------------------------------------------------
extern "C" void kernel_launch(void* const* d_in, const int* in_sizes, int n_in,
                              void* d_out, int out_size) {
    const float* x       = (const float*)d_in[0];
    const void*  eidx    = d_in[1];
    const void*  batchp  = d_in[2];
    const float* W_embed = (const float*)d_in[3];
    const float* b_embed = (const float*)d_in[4];
    const float* Wm      = (const float*)d_in[5];
    const float* bm      = (const float*)d_in[6];
    const float* W1      = (const float*)d_in[7];
    const float* b1      = (const float*)d_in[8];
    const float* W2      = (const float*)d_in[9];
    const float* b2      = (const float*)d_in[10];
    float* out = (float*)d_out;

    int nrows = in_sizes[0] / HH;
    if (nrows > NN) nrows = NN;

    const int nb_scan = (NN + 1023) / 1024;
    const int eg = (EE + 255) / 256;
    const int gx = (nrows + 127) / 128;

    zero_kernel<<<(NN + 255) / 256, 256>>>();
    detect_kernel<<<1, 256>>>(eidx, batchp);
    prep_kernel<<<(7 * HH * HH + 255) / 256, 256>>>(W_embed, Wm);
    gemm_embed<<<dim3(gx, 2), 256>>>(x, b_embed, nrows);   // launch #4 (ncu)

    convert_kernel<<<eg, 256>>>(eidx, batchp);
    scan1_kernel<<<nb_scan, 1024>>>();
    scan2_kernel<<<1, 128>>>(nb_scan);
    scan3_kernel<<<nb_scan, 1024>>>();
    fill_kernel<<<eg, 256>>>();

    for (int l = 0; l < LL; l++) {
        gemm_layer<<<dim3(gx, 4), 256>>>(1 + 2 * l, nrows);
        gather_relu<<<(nrows + 3) / 4, dim3(32, 4)>>>(bm + (size_t)l * HH, nrows);
    }

    pool_kernel<<<(NN + 511) / 512, 128>>>();
    r1_kernel<<<(BB * 2 * HH + 255) / 256, 256>>>(W1, b1);
    r2_kernel<<<(BB * MM + 255) / 256, 256>>>(W2, b2, out);
}

// round 9
// speedup vs baseline: 2.1032x; 1.0539x over previous
#include <cuda_runtime.h>
#include <cuda_fp16.h>
#include <math.h>

// Problem constants (fixed shapes)
#define NN 100000
#define EE 1600000
#define HH 128
#define BB 16
#define MM 2048
#define LL 3

// -------- static device scratch (no allocations allowed) --------
__device__ __half g_Ah[(size_t)NN * HH];   // h @ Wm_top (fp16)
__device__ __half g_Bh[(size_t)NN * HH];   // h @ Wm_bot (fp16)
__device__ __half g_hh[(size_t)NN * HH];   // node hidden state (fp16)
__device__ __half g_Wt[7 * HH * HH];       // W^T (fp16)
__device__ int    g_src[EE];
__device__ int    g_tgt[EE];
__device__ int    g_col[EE];
__device__ int    g_deg[NN];
__device__ int    g_off[NN];
__device__ int    g_cursor[NN];
__device__ int    g_batchi[NN];
__device__ int    g_bsums[128];
__device__ float  g_gsum[BB * HH];
__device__ int    g_cnt[BB];
__device__ float  g_t1[BB * 2 * HH];
__device__ int    g_flags;

// ----------------------------------------------------------------
__global__ void zero_kernel() {
    int i = blockIdx.x * blockDim.x + threadIdx.x;
    if (i < NN) g_deg[i] = 0;
    if (i < BB * HH) g_gsum[i] = 0.0f;
    if (i < BB) g_cnt[i] = 0;
    if (i == 0) g_flags = 0;
}

__global__ void detect_kernel(const void* __restrict__ ep, const void* __restrict__ bp) {
    int j = threadIdx.x;
    long long pos = (long long)j * (EE / 256);
    long long v = ((const long long*)ep)[pos];
    if (v < 0 || v >= NN) atomicOr(&g_flags, 1);
    long long bpos = (long long)(NN / 4) + j;
    long long bv = ((const long long*)bp)[bpos];
    if (bv < 0 || bv >= BB) atomicOr(&g_flags, 2);
}

// weight transpose to fp16
__global__ void prep_kernel(const float* __restrict__ We, const float* __restrict__ Wm) {
    int idx = blockIdx.x * blockDim.x + threadIdx.x;
    if (idx >= 7 * HH * HH) return;
    int mat = idx >> 14;
    int r = (idx >> 7) & 127;  // k
    int c = idx & 127;         // n
    float v;
    if (mat == 0) {
        v = We[r * HH + c];
    } else {
        int l = (mat - 1) >> 1;
        int hf = (mat - 1) & 1;
        v = Wm[((size_t)l * 2 * HH + hf * HH + r) * HH + c];
    }
    g_Wt[mat * HH * HH + c * HH + r] = __float2half_rn(v);
}

__global__ void convert_kernel(const void* __restrict__ ep, const void* __restrict__ bp) {
    int f = g_flags;
    long long i = (long long)blockIdx.x * blockDim.x + threadIdx.x;
    if (i < EE) {
        long long s, t;
        if (f & 1) {
            s = ((const int*)ep)[i];
            t = ((const int*)ep)[EE + i];
        } else {
            s = ((const long long*)ep)[i];
            t = ((const long long*)ep)[EE + i];
        }
        g_src[i] = (int)s;
        g_tgt[i] = (int)t;
        atomicAdd(&g_deg[(int)t], 1);
    }
    if (i < NN) {
        int b = (f & 2) ? ((const int*)bp)[i] : (int)((const long long*)bp)[i];
        g_batchi[i] = b;
        atomicAdd(&g_cnt[b], 1);
    }
}

__global__ void scan1_kernel() {
    __shared__ int sh[1024];
    int t = threadIdx.x;
    int i = blockIdx.x * 1024 + t;
    int v = (i < NN) ? g_deg[i] : 0;
    sh[t] = v;
    __syncthreads();
#pragma unroll
    for (int s = 1; s < 1024; s <<= 1) {
        int x = (t >= s) ? sh[t - s] : 0;
        __syncthreads();
        sh[t] += x;
        __syncthreads();
    }
    if (i < NN) g_off[i] = sh[t] - v;
    if (t == 1023) g_bsums[blockIdx.x] = sh[1023];
}

__global__ void scan2_kernel(int nb) {
    __shared__ int sh[128];
    int t = threadIdx.x;
    int v = (t < nb) ? g_bsums[t] : 0;
    sh[t] = v;
    __syncthreads();
#pragma unroll
    for (int s = 1; s < 128; s <<= 1) {
        int x = (t >= s) ? sh[t - s] : 0;
        __syncthreads();
        sh[t] += x;
        __syncthreads();
    }
    if (t < nb) g_bsums[t] = sh[t] - v;
}

__global__ void scan3_kernel() {
    int i = blockIdx.x * 1024 + threadIdx.x;
    if (i < NN) {
        int o = g_off[i] + g_bsums[blockIdx.x];
        g_off[i] = o;
        g_cursor[i] = o;
    }
}

__global__ void fill_kernel() {
    long long i = (long long)blockIdx.x * blockDim.x + threadIdx.x;
    if (i < EE) {
        int t = g_tgt[i];
        int p = atomicAdd(&g_cursor[t], 1);
        g_col[p] = g_src[i];
    }
}

// -------- shared GEMM helpers ----------------------------------------------
#define SASTRIDE 40

__device__ __forceinline__ unsigned smaddr(const void* p) {
    return (unsigned)__cvta_generic_to_shared(p);
}

#define LDMX4(R, addr)                                                           \
    asm volatile("ldmatrix.sync.aligned.m8n8.x4.shared.b16 {%0,%1,%2,%3}, [%4];" \
                 : "=r"((R)[0]), "=r"((R)[1]), "=r"((R)[2]), "=r"((R)[3])        \
                 : "r"(addr))

#define MMA16816(C, A, b0, b1)                                                   \
    asm volatile(                                                                \
        "mma.sync.aligned.m16n8k16.row.col.f32.f16.f16.f32 "                     \
        "{%0,%1,%2,%3}, {%4,%5,%6,%7}, {%8,%9}, {%0,%1,%2,%3};"                  \
        : "+f"((C)[0]), "+f"((C)[1]), "+f"((C)[2]), "+f"((C)[3])                 \
        : "r"((A)[0]), "r"((A)[1]), "r"((A)[2]), "r"((A)[3]), "r"(b0), "r"(b1))

// Double-buffered single-term fp16 mainloop. Block tile 128x64, warp tile 32x32.
#define GEMM_MAINLOOP(LOAD_STAGE, STORE_STAGE)                                    \
    LOAD_STAGE(0);                                                                \
    STORE_STAGE(0);                                                               \
    __syncthreads();                                                              \
    _Pragma("unroll") for (int kc = 0; kc < 4; kc++) {                            \
        if (kc < 3) LOAD_STAGE(kc + 1);                                           \
        const int s = kc & 1;                                                     \
        _Pragma("unroll") for (int ks = 0; ks < 2; ks++) {                        \
            const int kk = ks * 16;                                               \
            unsigned ah[2][4];                                                    \
            _Pragma("unroll") for (int f = 0; f < 2; f++) {                       \
                int row = wm * 32 + f * 16 + a_r;                                 \
                LDMX4(ah[f], smaddr(&sA[s][row * SASTRIDE + kk + a_k8]));         \
            }                                                                     \
            unsigned bh[2][4];                                                    \
            _Pragma("unroll") for (int nb = 0; nb < 2; nb++) {                    \
                int n = wn * 32 + nb * 16 + b_n;                                  \
                LDMX4(bh[nb], smaddr(&sW[s][n * SASTRIDE + kk + b_k8]));          \
            }                                                                     \
            _Pragma("unroll") for (int f = 0; f < 2; f++) {                       \
                _Pragma("unroll") for (int nb = 0; nb < 2; nb++) {                \
                    MMA16816(acc[f][nb * 2],     ah[f], bh[nb][0], bh[nb][1]);    \
                    MMA16816(acc[f][nb * 2 + 1], ah[f], bh[nb][2], bh[nb][3]);    \
                }                                                                 \
            }                                                                     \
        }                                                                         \
        if (kc < 3) {                                                             \
            STORE_STAGE((kc + 1) & 1);                                            \
            __syncthreads();                                                      \
        }                                                                         \
    }

// -------- embed GEMM: h = fp16(x) @ fp16(W_embed) + b -----------------------
// grid (gx, 2): y selects 64-col half. Writes g_hh (fp16).
__global__ void __launch_bounds__(256, 2) gemm_embed(const float* __restrict__ xin,
                                                     const float* __restrict__ bias,
                                                     int nrows) {
    __shared__ __align__(16) __half sA[2][128 * SASTRIDE];
    __shared__ __align__(16) __half sW[2][64 * SASTRIDE];

    const int colBase = blockIdx.y * 64;
    const __half* Wt = g_Wt + (size_t)colBase * HH;

    const int tid = threadIdx.x;
    const int wid = tid >> 5, lane = tid & 31;
    const int wm = wid >> 1, wn = wid & 1;
    const int rowBase = blockIdx.x * 128;

    const int s_r = tid >> 2;
    const int s_kq = (tid & 3) * 8;
    const int gr0 = rowBase + s_r;
    const int gr1 = gr0 + 64;

    float acc[2][4][4];
#pragma unroll
    for (int f = 0; f < 2; f++)
#pragma unroll
        for (int nf = 0; nf < 4; nf++)
#pragma unroll
            for (int q = 0; q < 4; q++) acc[f][nf][q] = 0.0f;

    const int a_r = (lane & 7) + ((lane >> 3) & 1) * 8;
    const int a_k8 = ((lane >> 4) & 1) * 8;
    const int b_n = (lane & 7) + ((lane >> 4) & 1) * 8;
    const int b_k8 = ((lane >> 3) & 1) * 8;

    uint4 ra0, ra1, rw;

#define CVT8(dst, gp)                                                             \
    do {                                                                          \
        float4 xa = *(const float4*)(gp);                                        \
        float4 xb = *(const float4*)((gp) + 4);                                  \
        __half2 p0 = __floats2half2_rn(xa.x, xa.y);                              \
        __half2 p1 = __floats2half2_rn(xa.z, xa.w);                              \
        __half2 p2 = __floats2half2_rn(xb.x, xb.y);                              \
        __half2 p3 = __floats2half2_rn(xb.z, xb.w);                              \
        dst = make_uint4(*(unsigned*)&p0, *(unsigned*)&p1,                        \
                         *(unsigned*)&p2, *(unsigned*)&p3);                       \
    } while (0)

#define E_LOAD_STAGE(kc)                                                          \
    do {                                                                          \
        int k0_ = (kc) * 32;                                                      \
        if (gr0 < nrows) CVT8(ra0, xin + (size_t)gr0 * HH + k0_ + s_kq);          \
        else ra0 = make_uint4(0, 0, 0, 0);                                        \
        if (gr1 < nrows) CVT8(ra1, xin + (size_t)gr1 * HH + k0_ + s_kq);          \
        else ra1 = make_uint4(0, 0, 0, 0);                                        \
        rw = *(const uint4*)(Wt + (size_t)s_r * HH + k0_ + s_kq);                 \
    } while (0)

#define E_STORE_STAGE(s)                                                          \
    do {                                                                          \
        *(uint4*)&sA[s][s_r * SASTRIDE + s_kq] = ra0;                             \
        *(uint4*)&sA[s][(s_r + 64) * SASTRIDE + s_kq] = ra1;                      \
        *(uint4*)&sW[s][s_r * SASTRIDE + s_kq] = rw;                              \
    } while (0)

    GEMM_MAINLOOP(E_LOAD_STAGE, E_STORE_STAGE)
#undef E_LOAD_STAGE
#undef E_STORE_STAGE
#undef CVT8

    const int gid = lane >> 2, qid = lane & 3;
#pragma unroll
    for (int f = 0; f < 2; f++) {
        int rbase = rowBase + wm * 32 + f * 16 + gid;
#pragma unroll
        for (int nf = 0; nf < 4; nf++) {
            int col = colBase + wn * 32 + nf * 8 + qid * 2;
            float bx = bias[col], by = bias[col + 1];
#pragma unroll
            for (int half_ = 0; half_ < 2; half_++) {
                int row = rbase + half_ * 8;
                if (row >= nrows) continue;
                *(__half2*)(g_hh + (size_t)row * HH + col) =
                    __floats2half2_rn(acc[f][nf][half_ * 2] + bx,
                                      acc[f][nf][half_ * 2 + 1] + by);
            }
        }
    }
}

// -------- layer GEMM: A/B = hh @ W (fp16), double-buffered ------------------
// grid (gx, 4): y>>1 selects matrix (A/B), y&1 selects 64-col half.
__global__ void __launch_bounds__(256, 3) gemm_layer(int mat0, int nrows) {
    __shared__ __align__(16) __half sA[2][128 * SASTRIDE];
    __shared__ __align__(16) __half sW[2][64 * SASTRIDE];

    const int matSel = blockIdx.y >> 1;
    const int colBase = (blockIdx.y & 1) * 64;
    const int mat = mat0 + matSel;
    const __half* Wt = g_Wt + (size_t)mat * HH * HH + (size_t)colBase * HH;

    const int tid = threadIdx.x;
    const int wid = tid >> 5, lane = tid & 31;
    const int wm = wid >> 1, wn = wid & 1;
    const int rowBase = blockIdx.x * 128;

    const int s_r = tid >> 2;
    const int s_kq = (tid & 3) * 8;
    const int gr0 = rowBase + s_r;
    const int gr1 = gr0 + 64;

    float acc[2][4][4];
#pragma unroll
    for (int f = 0; f < 2; f++)
#pragma unroll
        for (int nf = 0; nf < 4; nf++)
#pragma unroll
            for (int q = 0; q < 4; q++) acc[f][nf][q] = 0.0f;

    const int a_r = (lane & 7) + ((lane >> 3) & 1) * 8;
    const int a_k8 = ((lane >> 4) & 1) * 8;
    const int b_n = (lane & 7) + ((lane >> 4) & 1) * 8;
    const int b_k8 = ((lane >> 3) & 1) * 8;

    uint4 ra0, ra1, rw;

#define L_LOAD_STAGE(kc)                                                                   \
    do {                                                                                   \
        int k0_ = (kc) * 32;                                                               \
        ra0 = (gr0 < nrows) ? *(const uint4*)(g_hh + (size_t)gr0 * HH + k0_ + s_kq)        \
                            : make_uint4(0, 0, 0, 0);                                      \
        ra1 = (gr1 < nrows) ? *(const uint4*)(g_hh + (size_t)gr1 * HH + k0_ + s_kq)        \
                            : make_uint4(0, 0, 0, 0);                                      \
        rw = *(const uint4*)(Wt + (size_t)s_r * HH + k0_ + s_kq);                          \
    } while (0)

#define L_STORE_STAGE(s)                                                                   \
    do {                                                                                   \
        *(uint4*)&sA[s][s_r * SASTRIDE + s_kq] = ra0;                                      \
        *(uint4*)&sA[s][(s_r + 64) * SASTRIDE + s_kq] = ra1;                               \
        *(uint4*)&sW[s][s_r * SASTRIDE + s_kq] = rw;                                       \
    } while (0)

    GEMM_MAINLOOP(L_LOAD_STAGE, L_STORE_STAGE)
#undef L_LOAD_STAGE
#undef L_STORE_STAGE

    const int gid = lane >> 2, qid = lane & 3;
    __half* outh = matSel ? g_Bh : g_Ah;
#pragma unroll
    for (int f = 0; f < 2; f++) {
        int rbase = rowBase + wm * 32 + f * 16 + gid;
#pragma unroll
        for (int nf = 0; nf < 4; nf++) {
            int col = colBase + wn * 32 + nf * 8 + qid * 2;
#pragma unroll
            for (int half_ = 0; half_ < 2; half_++) {
                int row = rbase + half_ * 8;
                if (row >= nrows) continue;
                *(__half2*)(outh + (size_t)row * HH + col) =
                    __floats2half2_rn(acc[f][nf][half_ * 2], acc[f][nf][half_ * 2 + 1]);
            }
        }
    }
}

// -------- fused aggregate + residual + relu (atomic-free via CSR) -----------
__global__ void __launch_bounds__(256) gather_relu(const float* __restrict__ bm, int nrows) {
    int t = blockIdx.x * 8 + threadIdx.y;
    if (t >= nrows) return;
    int lane = threadIdx.x;
    int d = g_deg[t];
    int o = g_off[t];
    size_t base = (size_t)t * HH + lane * 4;

    float4 bmv = *(const float4*)(bm + lane * 4);
    uint2 bvp = *(const uint2*)(g_Bh + base);
    float2 bq0 = __half22float2(*(__half2*)&bvp.x);
    float2 bq1 = __half22float2(*(__half2*)&bvp.y);
    float dd = (float)d;
    float4 acc;
    acc.x = dd * (bq0.x + bmv.x);
    acc.y = dd * (bq0.y + bmv.y);
    acc.z = dd * (bq1.x + bmv.z);
    acc.w = dd * (bq1.y + bmv.w);

    int i = 0;
    for (; i + 4 <= d; i += 4) {
        int s0 = g_col[o + i];
        int s1 = g_col[o + i + 1];
        int s2 = g_col[o + i + 2];
        int s3 = g_col[o + i + 3];
        uint2 v0 = *(const uint2*)(g_Ah + (size_t)s0 * HH + lane * 4);
        uint2 v1 = *(const uint2*)(g_Ah + (size_t)s1 * HH + lane * 4);
        uint2 v2 = *(const uint2*)(g_Ah + (size_t)s2 * HH + lane * 4);
        uint2 v3 = *(const uint2*)(g_Ah + (size_t)s3 * HH + lane * 4);
        float2 a0 = __half22float2(*(__half2*)&v0.x), a1 = __half22float2(*(__half2*)&v0.y);
        float2 b0 = __half22float2(*(__half2*)&v1.x), b1 = __half22float2(*(__half2*)&v1.y);
        float2 c0 = __half22float2(*(__half2*)&v2.x), c1 = __half22float2(*(__half2*)&v2.y);
        float2 d0 = __half22float2(*(__half2*)&v3.x), d1 = __half22float2(*(__half2*)&v3.y);
        acc.x += (a0.x + b0.x) + (c0.x + d0.x);
        acc.y += (a0.y + b0.y) + (c0.y + d0.y);
        acc.z += (a1.x + b1.x) + (c1.x + d1.x);
        acc.w += (a1.y + b1.y) + (c1.y + d1.y);
    }
    for (; i < d; i++) {
        int s0 = g_col[o + i];
        uint2 v0 = *(const uint2*)(g_Ah + (size_t)s0 * HH + lane * 4);
        float2 a0 = __half22float2(*(__half2*)&v0.x);
        float2 a1 = __half22float2(*(__half2*)&v0.y);
        acc.x += a0.x;
        acc.y += a0.y;
        acc.z += a1.x;
        acc.w += a1.y;
    }

    uint2 hh2 = *(const uint2*)(g_hh + base);
    float2 h0 = __half22float2(*(__half2*)&hh2.x);
    float2 h1 = __half22float2(*(__half2*)&hh2.y);
    float4 v;
    v.x = fmaxf(h0.x + acc.x, 0.0f);
    v.y = fmaxf(h0.y + acc.y, 0.0f);
    v.z = fmaxf(h1.x + acc.z, 0.0f);
    v.w = fmaxf(h1.y + acc.w, 0.0f);

    __half2 o0 = __floats2half2_rn(v.x, v.y);
    __half2 o1 = __floats2half2_rn(v.z, v.w);
    uint2 ph;
    ph.x = *(unsigned*)&o0;
    ph.y = *(unsigned*)&o1;
    *(uint2*)(g_hh + base) = ph;
}

// -------- per-graph mean pool --------
__global__ void __launch_bounds__(128) pool_kernel() {
    int c = threadIdx.x;
    int n0 = blockIdx.x * 512;
    if (n0 >= NN) return;
    int n1 = n0 + 512;
    if (n1 > NN) n1 = NN;
    int curb = g_batchi[n0];
    float acc = 0.0f;
    for (int n = n0; n < n1; n++) {
        int b = g_batchi[n];
        if (b != curb) {
            atomicAdd(&g_gsum[curb * HH + c], acc);
            acc = 0.0f;
            curb = b;
        }
        acc += __half2float(g_hh[(size_t)n * HH + c]);
    }
    atomicAdd(&g_gsum[curb * HH + c], acc);
}

// -------- readout --------
__global__ void r1_kernel(const float* __restrict__ W1, const float* __restrict__ b1) {
    int idx = blockIdx.x * blockDim.x + threadIdx.x;
    if (idx >= BB * 2 * HH) return;
    int b = idx >> 8;
    int j = idx & 255;
    int cnt = g_cnt[b];
    float inv = 1.0f / (float)(cnt > 0 ? cnt : 1);
    float s = 0.0f;
#pragma unroll 8
    for (int k = 0; k < HH; k++) s = fmaf(g_gsum[b * HH + k], W1[(size_t)k * 256 + j], s);
    s = s * inv + b1[j];
    g_t1[idx] = s > 0.0f ? s : 0.0f;
}

__global__ void r2_kernel(const float* __restrict__ W2, const float* __restrict__ b2,
                          float* __restrict__ out) {
    int idx = blockIdx.x * blockDim.x + threadIdx.x;
    if (idx >= BB * MM) return;
    int b = idx >> 11;
    int m = idx & 2047;
    float s = b2[m];
#pragma unroll 8
    for (int k = 0; k < 2 * HH; k++)
        s = fmaf(g_t1[b * 2 * HH + k], W2[(size_t)k * MM + m], s);
    float sig = 1.0f / (1.0f + expf(-s));
    out[idx] = sig * 6.283185307179586f;
}

// ----------------------------------------------------------------
extern "C" void kernel_launch(void* const* d_in, const int* in_sizes, int n_in,
                              void* d_out, int out_size) {
    const float* x       = (const float*)d_in[0];
    const void*  eidx    = d_in[1];
    const void*  batchp  = d_in[2];
    const float* W_embed = (const float*)d_in[3];
    const float* b_embed = (const float*)d_in[4];
    const float* Wm      = (const float*)d_in[5];
    const float* bm      = (const float*)d_in[6];
    const float* W1      = (const float*)d_in[7];
    const float* b1      = (const float*)d_in[8];
    const float* W2      = (const float*)d_in[9];
    const float* b2      = (const float*)d_in[10];
    float* out = (float*)d_out;

    int nrows = in_sizes[0] / HH;
    if (nrows > NN) nrows = NN;

    const int nb_scan = (NN + 1023) / 1024;
    const int eg = (EE + 255) / 256;
    const int gx = (nrows + 127) / 128;

    zero_kernel<<<(NN + 255) / 256, 256>>>();
    detect_kernel<<<1, 256>>>(eidx, batchp);
    prep_kernel<<<(7 * HH * HH + 255) / 256, 256>>>(W_embed, Wm);
    gemm_embed<<<dim3(gx, 2), 256>>>(x, b_embed, nrows);   // launch #4 (ncu)

    convert_kernel<<<eg, 256>>>(eidx, batchp);
    scan1_kernel<<<nb_scan, 1024>>>();
    scan2_kernel<<<1, 128>>>(nb_scan);
    scan3_kernel<<<nb_scan, 1024>>>();
    fill_kernel<<<eg, 256>>>();

    for (int l = 0; l < LL; l++) {
        gemm_layer<<<dim3(gx, 4), 256>>>(1 + 2 * l, nrows);
        gather_relu<<<(nrows + 7) / 8, dim3(32, 8)>>>(bm + (size_t)l * HH, nrows);
    }

    pool_kernel<<<(NN + 511) / 512, 128>>>();
    r1_kernel<<<(BB * 2 * HH + 255) / 256, 256>>>(W1, b1);
    r2_kernel<<<(BB * MM + 255) / 256, 256>>>(W2, b2, out);
}